// round 2
// baseline (speedup 1.0000x reference)
#include <cuda_runtime.h>
#include <math.h>

// ---------------- problem constants ----------------
// S=2048, B=2, H=2048, NH=16, D=128, FF=8192, M=2048
// rows R = S*B = M*B = 4096
#define CH   2048
#define CFF  8192
#define CR   4096
#define CS   2048
#define CMM  2048
#define CNH  16
#define CD   128
#define NBATCH 32            // B*NH
#define INV_NORM 0.08838834764831843f   // 1/sqrt(128)

// ---------------- device scratch (no cudaMalloc allowed) ----------------
__device__ float g_ln    [CR * CH];          //  33.5 MB
__device__ float g_hidden[CR * CFF];         // 134   MB
__device__ float g_x1    [CR * CH];          //  33.5 MB
__device__ float g_q     [CR * CH];          //  33.5 MB
__device__ float g_kv    [CR * 2 * CH];      //  67   MB
__device__ float g_scores[NBATCH * CS * CMM];// 536   MB
__device__ float g_ctx   [CR * CH];          //  33.5 MB
__device__ float g_x2    [CR * CH];          //  33.5 MB
__device__ int   g_mask_mode;                // 0=u8, 1=i32, 2=f32

// ---------------- helpers ----------------
__device__ __forceinline__ float gelu_f(float x) {
    // JAX default gelu (approximate=True, tanh form)
    float x3 = x * x * x;
    float t = tanhf(0.7978845608028654f * (x + 0.044715f * x3));
    return 0.5f * x * (1.0f + t);
}

__device__ __forceinline__ float block_sum(float v, float* sh) {
    #pragma unroll
    for (int o = 16; o > 0; o >>= 1) v += __shfl_xor_sync(0xffffffffu, v, o);
    int w = threadIdx.x >> 5;
    if ((threadIdx.x & 31) == 0) sh[w] = v;
    __syncthreads();
    if (w == 0) {
        float r = (threadIdx.x < 8) ? sh[threadIdx.x] : 0.0f;
        #pragma unroll
        for (int o = 4; o > 0; o >>= 1) r += __shfl_xor_sync(0xffffffffu, r, o);
        if (threadIdx.x == 0) sh[0] = r;
    }
    __syncthreads();
    float r = sh[0];
    __syncthreads();
    return r;
}

__device__ __forceinline__ float block_max(float v, float* sh) {
    #pragma unroll
    for (int o = 16; o > 0; o >>= 1) v = fmaxf(v, __shfl_xor_sync(0xffffffffu, v, o));
    int w = threadIdx.x >> 5;
    if ((threadIdx.x & 31) == 0) sh[w] = v;
    __syncthreads();
    if (w == 0) {
        float r = (threadIdx.x < 8) ? sh[threadIdx.x] : -3.4e38f;
        #pragma unroll
        for (int o = 4; o > 0; o >>= 1) r = fmaxf(r, __shfl_xor_sync(0xffffffffu, r, o));
        if (threadIdx.x == 0) sh[0] = r;
    }
    __syncthreads();
    float r = sh[0];
    __syncthreads();
    return r;
}

// ---------------- mask dtype detector ----------------
__global__ void detect_mask_k(const unsigned int* __restrict__ m) {
    __shared__ int sF, sB;
    if (threadIdx.x == 0) { sF = 0; sB = 0; }
    __syncthreads();
    for (int i = threadIdx.x; i < 2048; i += 256) {
        unsigned v = m[i];
        if (v == 0x3F800000u) sF = 1;
        else if (v > 1u) sB = 1;
    }
    __syncthreads();
    if (threadIdx.x == 0) g_mask_mode = sF ? 2 : (sB ? 0 : 1);
}

// ---------------- SGEMM: 128x128 tile, 256 thr, 8x8 microtile ----------------
// BT=false: B is [K,N] row-major (NN).  BT=true: B is [N,K] row-major (NT).
// C = f(alpha*A@B(^T) + bias) + resid,  f = gelu or identity
template<bool BT, bool GELU>
__global__ void __launch_bounds__(256)
gemm_k(const float* __restrict__ Ag, const float* __restrict__ Bg,
       float* __restrict__ Cg, int K, int lda, int ldb, int ldc,
       long long bsA, long long bsB, long long bsC,
       const float* __restrict__ bias,
       const float* __restrict__ resid, int ldr,
       float alpha)
{
    __shared__ __align__(16) float As[16][128];
    __shared__ __align__(16) float Bs[16][128];

    const int tid = threadIdx.x;
    const int tx = tid & 15, ty = tid >> 4;
    const int m0 = blockIdx.y * 128, n0 = blockIdx.x * 128;

    const float* A = Ag + (long long)blockIdx.z * bsA;
    const float* B = Bg + (long long)blockIdx.z * bsB;
    float*       C = Cg + (long long)blockIdx.z * bsC;

    // loader indices: two float4 per thread for each tile
    const int f0 = tid, f1 = tid + 256;
    const int ar0 = f0 >> 2, ak0 = (f0 & 3) * 4;
    const int ar1 = f1 >> 2, ak1 = (f1 & 3) * 4;

    const float* ap0 = A + (long long)(m0 + ar0) * lda + ak0;
    const float* ap1 = A + (long long)(m0 + ar1) * lda + ak1;

    const float* bp0; const float* bp1;
    int bk0, bc0, bk1, bc1;   // NN mapping
    if (BT) {
        bp0 = B + (long long)(n0 + ar0) * ldb + ak0;
        bp1 = B + (long long)(n0 + ar1) * ldb + ak1;
        bk0 = bc0 = bk1 = bc1 = 0; // unused
    } else {
        bk0 = f0 >> 5; bc0 = (f0 & 31) * 4;
        bk1 = f1 >> 5; bc1 = (f1 & 31) * 4;
        bp0 = B + (long long)bk0 * ldb + n0 + bc0;
        bp1 = B + (long long)bk1 * ldb + n0 + bc1;
    }

    float acc[8][8] = {};

    for (int k0 = 0; k0 < K; k0 += 16) {
        float4 va0 = *(const float4*)ap0;
        float4 va1 = *(const float4*)ap1;
        float4 vb0 = *(const float4*)bp0;
        float4 vb1 = *(const float4*)bp1;

        As[ak0+0][ar0] = va0.x; As[ak0+1][ar0] = va0.y;
        As[ak0+2][ar0] = va0.z; As[ak0+3][ar0] = va0.w;
        As[ak1+0][ar1] = va1.x; As[ak1+1][ar1] = va1.y;
        As[ak1+2][ar1] = va1.z; As[ak1+3][ar1] = va1.w;

        if (BT) {
            Bs[ak0+0][ar0] = vb0.x; Bs[ak0+1][ar0] = vb0.y;
            Bs[ak0+2][ar0] = vb0.z; Bs[ak0+3][ar0] = vb0.w;
            Bs[ak1+0][ar1] = vb1.x; Bs[ak1+1][ar1] = vb1.y;
            Bs[ak1+2][ar1] = vb1.z; Bs[ak1+3][ar1] = vb1.w;
        } else {
            *(float4*)&Bs[bk0][bc0] = vb0;
            *(float4*)&Bs[bk1][bc1] = vb1;
        }
        __syncthreads();

        #pragma unroll
        for (int kk = 0; kk < 16; kk++) {
            float a[8], b[8];
            *(float4*)(a)     = *(const float4*)&As[kk][ty * 4];
            *(float4*)(a + 4) = *(const float4*)&As[kk][64 + ty * 4];
            *(float4*)(b)     = *(const float4*)&Bs[kk][tx * 4];
            *(float4*)(b + 4) = *(const float4*)&Bs[kk][64 + tx * 4];
            #pragma unroll
            for (int i = 0; i < 8; i++)
                #pragma unroll
                for (int j = 0; j < 8; j++)
                    acc[i][j] = fmaf(a[i], b[j], acc[i][j]);
        }
        __syncthreads();

        ap0 += 16; ap1 += 16;
        if (BT) { bp0 += 16; bp1 += 16; }
        else    { bp0 += (long long)16 * ldb; bp1 += (long long)16 * ldb; }
    }

    // epilogue
    #pragma unroll
    for (int i = 0; i < 8; i++) {
        int rl = (i < 4) ? (ty * 4 + i) : (64 + ty * 4 + i - 4);
        long long rowoff = (long long)(m0 + rl) * ldc;
        long long resoff = (long long)(m0 + rl) * ldr;
        #pragma unroll
        for (int j = 0; j < 8; j++) {
            int cl = (j < 4) ? (tx * 4 + j) : (64 + tx * 4 + j - 4);
            int cn = n0 + cl;
            float v = acc[i][j] * alpha;
            if (bias)  v += bias[cn];
            if (GELU)  v = gelu_f(v);
            if (resid) v += resid[resoff + cn];
            C[rowoff + cn] = v;
        }
    }
}

// ---------------- LayerNorm over width 2048 ----------------
__global__ void __launch_bounds__(256)
ln_k(const float* __restrict__ X, const float* __restrict__ gg,
     const float* __restrict__ bb, float* __restrict__ Y)
{
    __shared__ float sh[8];
    long long base = (long long)blockIdx.x * CH;
    int c0 = threadIdx.x * 8;
    float v[8];
    *(float4*)(v)     = *(const float4*)(X + base + c0);
    *(float4*)(v + 4) = *(const float4*)(X + base + c0 + 4);

    float s = 0.f;
    #pragma unroll
    for (int i = 0; i < 8; i++) s += v[i];
    s = block_sum(s, sh);
    float mu = s * (1.0f / CH);

    float d[8], s2 = 0.f;
    #pragma unroll
    for (int i = 0; i < 8; i++) { d[i] = v[i] - mu; s2 += d[i] * d[i]; }
    s2 = block_sum(s2, sh);
    float rstd = rsqrtf(s2 * (1.0f / CH) + 1e-5f);

    float o[8];
    #pragma unroll
    for (int i = 0; i < 8; i++) o[i] = d[i] * rstd * gg[c0 + i] + bb[c0 + i];
    *(float4*)(Y + base + c0)     = *(float4*)(o);
    *(float4*)(Y + base + c0 + 4) = *(float4*)(o + 4);
}

// ---------------- L2 normalize contiguous chunks of 128 floats ----------------
__global__ void __launch_bounds__(256)
l2_k(float* __restrict__ X)
{
    long long chunk = (long long)blockIdx.x * 8 + (threadIdx.x >> 5);
    int lane = threadIdx.x & 31;
    float4* p = (float4*)(X + chunk * 128) + lane;
    float4 v = *p;
    float s = v.x * v.x + v.y * v.y + v.z * v.z + v.w * v.w;
    #pragma unroll
    for (int o = 16; o > 0; o >>= 1) s += __shfl_xor_sync(0xffffffffu, s, o);
    float r = rsqrtf(s + 1e-12f);
    v.x *= r; v.y *= r; v.z *= r; v.w *= r;
    *p = v;
}

// ---------------- masked softmax over M=2048 ----------------
__global__ void __launch_bounds__(256)
softmax_k(float* __restrict__ Sc, const void* __restrict__ maskp)
{
    __shared__ float sh[8];
    int r = blockIdx.x;              // z*2048 + s, z = b*NH + h
    int z = r >> 11, s = r & 2047;
    int b = z >> 4;
    float* row = Sc + (long long)r * CMM;
    long long moff = ((long long)b * CS + s) * CMM;
    int mode = g_mask_mode;
    int c0 = threadIdx.x * 8;

    float v[8];
    *(float4*)(v)     = *(float4*)(row + c0);
    *(float4*)(v + 4) = *(float4*)(row + c0 + 4);

    if (mode == 0) {
        const unsigned char* mp = (const unsigned char*)maskp + moff + c0;
        #pragma unroll
        for (int i = 0; i < 8; i++) if (mp[i]) v[i] = -1e4f;
    } else if (mode == 1) {
        const int* mp = (const int*)maskp + moff + c0;
        #pragma unroll
        for (int i = 0; i < 8; i++) if (mp[i]) v[i] = -1e4f;
    } else {
        const float* mp = (const float*)maskp + moff + c0;
        #pragma unroll
        for (int i = 0; i < 8; i++) if (mp[i] != 0.0f) v[i] = -1e4f;
    }

    float mx = -3.4e38f;
    #pragma unroll
    for (int i = 0; i < 8; i++) mx = fmaxf(mx, v[i]);
    mx = block_max(mx, sh);

    float e[8], sum = 0.f;
    #pragma unroll
    for (int i = 0; i < 8; i++) { e[i] = __expf(v[i] - mx); sum += e[i]; }
    sum = block_sum(sum, sh);
    float inv = 1.0f / sum;

    float o[8];
    #pragma unroll
    for (int i = 0; i < 8; i++) o[i] = e[i] * inv;
    *(float4*)(row + c0)     = *(float4*)(o);
    *(float4*)(row + c0 + 4) = *(float4*)(o + 4);
}

// ---------------- launcher ----------------
extern "C" void kernel_launch(void* const* d_in, const int* in_sizes, int n_in,
                              void* d_out, int out_size)
{
    const float* x      = (const float*)d_in[0];
    const float* memh   = (const float*)d_in[1];
    const void*  mask   = d_in[2];
    const float* ln1g   = (const float*)d_in[3];
    const float* ln1b   = (const float*)d_in[4];
    const float* ln2g   = (const float*)d_in[5];
    const float* ln2b   = (const float*)d_in[6];
    const float* ln3g   = (const float*)d_in[7];
    const float* ln3b   = (const float*)d_in[8];
    const float* w1i    = (const float*)d_in[9];
    const float* b1i    = (const float*)d_in[10];
    const float* w1o    = (const float*)d_in[11];
    const float* b1o    = (const float*)d_in[12];
    const float* wq     = (const float*)d_in[13];
    const float* bq     = (const float*)d_in[14];
    const float* wkv    = (const float*)d_in[15];
    const float* bkv    = (const float*)d_in[16];
    const float* wd     = (const float*)d_in[17];
    const float* bd     = (const float*)d_in[18];
    const float* w2i    = (const float*)d_in[19];
    const float* b2i    = (const float*)d_in[20];
    const float* w2o    = (const float*)d_in[21];
    const float* b2o    = (const float*)d_in[22];
    float* out = (float*)d_out;

    float *lnb, *hid, *x1, *q, *kv, *sc, *ctx, *x2;
    cudaGetSymbolAddress((void**)&lnb, g_ln);
    cudaGetSymbolAddress((void**)&hid, g_hidden);
    cudaGetSymbolAddress((void**)&x1,  g_x1);
    cudaGetSymbolAddress((void**)&q,   g_q);
    cudaGetSymbolAddress((void**)&kv,  g_kv);
    cudaGetSymbolAddress((void**)&sc,  g_scores);
    cudaGetSymbolAddress((void**)&ctx, g_ctx);
    cudaGetSymbolAddress((void**)&x2,  g_x2);

    // mask dtype probe (deterministic, capturable)
    detect_mask_k<<<1, 256>>>((const unsigned int*)mask);

    // x = mlp1(ln1(x))  -- NO residual
    ln_k<<<CR, 256>>>(x, ln1g, ln1b, lnb);
    gemm_k<false, true ><<<dim3(CFF/128, CR/128, 1), 256>>>(
        lnb, w1i, hid, CH, CH, CFF, CFF, 0, 0, 0, b1i, nullptr, 0, 1.0f);
    gemm_k<false, false><<<dim3(CH/128, CR/128, 1), 256>>>(
        hid, w1o, x1, CFF, CFF, CH, CH, 0, 0, 0, b1o, nullptr, 0, 1.0f);

    // memory attention
    ln_k<<<CR, 256>>>(x1, ln2g, ln2b, lnb);
    gemm_k<false, false><<<dim3(CH/128, CR/128, 1), 256>>>(
        lnb, wq, q, CH, CH, CH, CH, 0, 0, 0, bq, nullptr, 0, 1.0f);
    l2_k<<<CR * CH / 128 / 8, 256>>>(q);

    gemm_k<false, false><<<dim3(2*CH/128, CR/128, 1), 256>>>(
        memh, wkv, kv, CH, CH, 2*CH, 2*CH, 0, 0, 0, bkv, nullptr, 0, 1.0f);
    l2_k<<<CR * 2 * CH / 128 / 8, 256>>>(kv);

    // scores[z, s, m] = q . k / sqrt(D)   (batched NT, z = b*NH+h)
    gemm_k<true, false><<<dim3(CMM/128, CS/128, NBATCH), 256>>>(
        q, kv, sc, CD, 2*CH /*lda: stride over s*/, 2*2*CH /*ldb: stride over m = 8192*/,
        CMM, 128 /*bsA*/, 256 /*bsB*/, (long long)CS*CMM /*bsC*/,
        nullptr, nullptr, 0, INV_NORM);

    softmax_k<<<NBATCH * CS, 256>>>(sc, mask);

    // ctx[z, s, d] = probs @ v  (batched NN)
    gemm_k<false, false><<<dim3(CD/128, CS/128, NBATCH), 256>>>(
        sc, kv + 128, ctx, CMM, CMM, 2*2*CH /*ldb=8192*/, 2*CH /*ldc: stride over s*/,
        (long long)CS*CMM, 256, 128, nullptr, nullptr, 0, 1.0f);

    // x2 = x1 + ctx @ w_dense + b_dense
    gemm_k<false, false><<<dim3(CH/128, CR/128, 1), 256>>>(
        ctx, wd, x2, CH, CH, CH, CH, 0, 0, 0, bd, x1, CH, 1.0f);

    // out = x2 + mlp2(ln3(x2))
    ln_k<<<CR, 256>>>(x2, ln3g, ln3b, lnb);
    gemm_k<false, true ><<<dim3(CFF/128, CR/128, 1), 256>>>(
        lnb, w2i, hid, CH, CH, CFF, CFF, 0, 0, 0, b2i, nullptr, 0, 1.0f);
    gemm_k<false, false><<<dim3(CH/128, CR/128, 1), 256>>>(
        hid, w2o, out, CFF, CFF, CH, CH, 0, 0, 0, b2o, x2, CH, 1.0f);
}

// round 5
// speedup vs baseline: 2.8564x; 2.8564x over previous
#include <cuda_runtime.h>
#include <cstdint>
#include <math.h>

// ---------------- problem constants ----------------
#define CH   2048
#define CFF  8192
#define CR   4096
#define CS   2048
#define CMM  2048
#define CD   128
#define NBATCH 32
#define INV_NORM 0.08838834764831843f

#define NSTG 3
#define LDSW 36                      // smem row stride (floats): conflict-free
#define ASZ  (128 * LDSW)            // floats per A (or B) tile in smem
#define STGF (2 * ASZ)               // floats per stage
#define SMEMB (NSTG * STGF * 4)      // 110592 bytes

// ---------------- device scratch ----------------
__device__ float g_ln    [CR * CH];
__device__ float g_hidden[CR * CFF];
__device__ float g_x1    [CR * CH];
__device__ float g_q     [CR * CH];
__device__ float g_kv    [CR * 2 * CH];
__device__ float g_scores[(long long)NBATCH * CS * CMM];
__device__ float g_ctx   [CR * CH];
__device__ float g_x2    [CR * CH];
__device__ float g_memr  [CR * CH];
__device__ float g_w1iT  [CFF * CH];
__device__ float g_w1oT  [CH * CFF];
__device__ float g_wqT   [CH * CH];
__device__ float g_wkvT  [2 * CH * CH];
__device__ float g_wdT   [CH * CH];
__device__ float g_w2iT  [CFF * CH];
__device__ float g_w2oT  [CH * CFF];
__device__ float g_vT    [(long long)NBATCH * CD * CMM];
__device__ int   g_mask_mode;

// ---------------- helpers ----------------
__device__ __forceinline__ float rnd_tf32(float x) {
    uint32_t u;
    asm("cvt.rna.tf32.f32 %0, %1;" : "=r"(u) : "f"(x));
    return __uint_as_float(u);
}
__device__ __forceinline__ float gelu_f(float x) {
    float x3 = x * x * x;
    float t = tanhf(0.7978845608028654f * (x + 0.044715f * x3));
    return 0.5f * x * (1.0f + t);
}
__device__ __forceinline__ uint32_t smem_u32(const void* p) {
    uint32_t a;
    asm("{ .reg .u64 t; cvta.to.shared.u64 t, %1; cvt.u32.u64 %0, t; }" : "=r"(a) : "l"(p));
    return a;
}

__device__ __forceinline__ float block_sum(float v, float* sh) {
    #pragma unroll
    for (int o = 16; o > 0; o >>= 1) v += __shfl_xor_sync(0xffffffffu, v, o);
    int w = threadIdx.x >> 5;
    if ((threadIdx.x & 31) == 0) sh[w] = v;
    __syncthreads();
    if (w == 0) {
        float r = (threadIdx.x < 8) ? sh[threadIdx.x] : 0.0f;
        #pragma unroll
        for (int o = 4; o > 0; o >>= 1) r += __shfl_xor_sync(0xffffffffu, r, o);
        if (threadIdx.x == 0) sh[0] = r;
    }
    __syncthreads();
    float r = sh[0]; __syncthreads(); return r;
}
__device__ __forceinline__ float block_max(float v, float* sh) {
    #pragma unroll
    for (int o = 16; o > 0; o >>= 1) v = fmaxf(v, __shfl_xor_sync(0xffffffffu, v, o));
    int w = threadIdx.x >> 5;
    if ((threadIdx.x & 31) == 0) sh[w] = v;
    __syncthreads();
    if (w == 0) {
        float r = (threadIdx.x < 8) ? sh[threadIdx.x] : -3.4e38f;
        #pragma unroll
        for (int o = 4; o > 0; o >>= 1) r = fmaxf(r, __shfl_xor_sync(0xffffffffu, r, o));
        if (threadIdx.x == 0) sh[0] = r;
    }
    __syncthreads();
    float r = sh[0]; __syncthreads(); return r;
}

// ---------------- mask dtype detector ----------------
__global__ void detect_mask_k(const unsigned int* __restrict__ m) {
    __shared__ int sF, sB;
    if (threadIdx.x == 0) { sF = 0; sB = 0; }
    __syncthreads();
    for (int i = threadIdx.x; i < 2048; i += 256) {
        unsigned v = m[i];
        if (v == 0x3F800000u) sF = 1;
        else if (v > 1u) sB = 1;
    }
    __syncthreads();
    if (threadIdx.x == 0) g_mask_mode = sF ? 2 : (sB ? 0 : 1);
}

// ---------------- tf32 mma.sync GEMM (NT form) ----------------
// C[m,n] = f(alpha * sum_k A[m,k]*B[n,k] + bias[n]) (+ resid).
// 128x128x32 CTA tile, 3-stage cp.async, 8 warps each 32(M)x64(N).
template<bool GELU, bool ROUND>
__global__ void __launch_bounds__(256, 1)
mgemm_k(const float* __restrict__ Ag, const float* __restrict__ Bg,
        float* __restrict__ Cg, int K, int lda, int ldb, int ldc,
        long long bsA, long long bsB, long long bsC,
        const float* __restrict__ bias, const float* __restrict__ resid,
        int ldr, float alpha)
{
    extern __shared__ float sm[];
    const int tid = threadIdx.x, lane = tid & 31, wid = tid >> 5;
    const int m0 = blockIdx.y * 128, n0 = blockIdx.x * 128;
    const int wm = (wid & 3) * 32, wn = (wid >> 2) * 64;

    const float* A = Ag + (long long)blockIdx.z * bsA;
    const float* B = Bg + (long long)blockIdx.z * bsB;
    float*       C = Cg + (long long)blockIdx.z * bsC;

    // loader setup: 2048 16B-chunks per stage (A:1024, B:1024), 8 per thread
    const float* srcp[8];
    uint32_t dsto[8];
    const uint32_t sbase = smem_u32(sm);
    #pragma unroll
    for (int j = 0; j < 8; j++) {
        int g = tid + 256 * j;
        int isB = (g >= 1024);
        int gg = g - (isB ? 1024 : 0);
        int row = gg >> 3, kc = (gg & 7) * 4;
        srcp[j] = (isB ? B + (long long)(n0 + row) * ldb
                       : A + (long long)(m0 + row) * lda) + kc;
        dsto[j] = sbase + (uint32_t)(((isB ? ASZ : 0) + row * LDSW + kc) * 4);
    }

    const int KT = K >> 5;

    #define ISSUE(IT, SG) do { \
        uint32_t stoff = (uint32_t)(SG) * (STGF * 4); \
        long long koff = (long long)(IT) * 32; \
        _Pragma("unroll") \
        for (int j = 0; j < 8; j++) { \
            asm volatile("cp.async.cg.shared.global [%0], [%1], 16;" \
                :: "r"(dsto[j] + stoff), "l"(srcp[j] + koff)); \
        } \
        asm volatile("cp.async.commit_group;" ::: "memory"); \
    } while (0)

    // prologue: 2 stages in flight
    ISSUE(0, 0);
    ISSUE(1, 1);

    float acc[2][8][4];
    #pragma unroll
    for (int t = 0; t < 2; t++)
        #pragma unroll
        for (int n = 0; n < 8; n++)
            #pragma unroll
            for (int j = 0; j < 4; j++) acc[t][n][j] = 0.0f;

    const int r4 = lane >> 2, c4 = lane & 3;

    for (int it = 0; it < KT; it++) {
        int sg = it % NSTG;
        asm volatile("cp.async.wait_group 1;" ::: "memory");
        __syncthreads();
        if (it + 2 < KT) { ISSUE(it + 2, (it + 2) % NSTG); }
        else { asm volatile("cp.async.commit_group;" ::: "memory"); }

        const float* as_ = sm + sg * STGF;
        const float* bs_ = as_ + ASZ;
        #pragma unroll
        for (int ks = 0; ks < 4; ks++) {
            int k0 = ks * 8 + c4;
            uint32_t a[2][4], b[8][2];
            #pragma unroll
            for (int t = 0; t < 2; t++) {
                int rr = wm + t * 16 + r4;
                a[t][0] = __float_as_uint(as_[rr * LDSW + k0]);
                a[t][1] = __float_as_uint(as_[(rr + 8) * LDSW + k0]);
                a[t][2] = __float_as_uint(as_[rr * LDSW + k0 + 4]);
                a[t][3] = __float_as_uint(as_[(rr + 8) * LDSW + k0 + 4]);
            }
            #pragma unroll
            for (int n = 0; n < 8; n++) {
                int rn = wn + n * 8 + r4;
                b[n][0] = __float_as_uint(bs_[rn * LDSW + k0]);
                b[n][1] = __float_as_uint(bs_[rn * LDSW + k0 + 4]);
            }
            #pragma unroll
            for (int t = 0; t < 2; t++)
                #pragma unroll
                for (int n = 0; n < 8; n++) {
                    asm volatile(
                        "mma.sync.aligned.m16n8k8.row.col.f32.tf32.tf32.f32 "
                        "{%0,%1,%2,%3}, {%4,%5,%6,%7}, {%8,%9}, {%0,%1,%2,%3};"
                        : "+f"(acc[t][n][0]), "+f"(acc[t][n][1]),
                          "+f"(acc[t][n][2]), "+f"(acc[t][n][3])
                        : "r"(a[t][0]), "r"(a[t][1]), "r"(a[t][2]), "r"(a[t][3]),
                          "r"(b[n][0]), "r"(b[n][1]));
                }
        }
        __syncthreads();
    }

    // ---- epilogue ----
    #pragma unroll
    for (int t = 0; t < 2; t++) {
        int row = m0 + wm + t * 16 + r4;
        #pragma unroll
        for (int n = 0; n < 8; n++) {
            int col = n0 + wn + n * 8 + c4 * 2;
            float b0 = bias ? bias[col] : 0.0f;
            float b1 = bias ? bias[col + 1] : 0.0f;
            #pragma unroll
            for (int h = 0; h < 2; h++) {           // h=0: rows r, h=1: rows r+8
                int rr = row + h * 8;
                float v0 = acc[t][n][h * 2 + 0] * alpha + b0;
                float v1 = acc[t][n][h * 2 + 1] * alpha + b1;
                if (GELU) { v0 = gelu_f(v0); v1 = gelu_f(v1); }
                if (resid) {
                    long long ro = (long long)rr * ldr + col;
                    v0 += resid[ro]; v1 += resid[ro + 1];
                }
                if (ROUND) { v0 = rnd_tf32(v0); v1 = rnd_tf32(v1); }
                *(float2*)(C + (long long)rr * ldc + col) = make_float2(v0, v1);
            }
        }
    }
    #undef ISSUE
}

// ---------------- transpose (+ tf32 round) ----------------
__global__ void transpose_k(const float* __restrict__ in, float* __restrict__ out,
                            int R, int Cc)
{
    __shared__ float t[32][33];
    int c0 = blockIdx.x * 32, r0 = blockIdx.y * 32;
    int x = threadIdx.x, y = threadIdx.y;
    #pragma unroll
    for (int dy = 0; dy < 32; dy += 8)
        t[y + dy][x] = in[(long long)(r0 + y + dy) * Cc + c0 + x];
    __syncthreads();
    #pragma unroll
    for (int dy = 0; dy < 32; dy += 8)
        out[(long long)(c0 + y + dy) * R + r0 + x] = rnd_tf32(t[x][y + dy]);
}

// vT[z][d][m] = v(m, z, d) from kv layout
__global__ void vtrans_k(const float* __restrict__ kv, float* __restrict__ vT)
{
    __shared__ float t[32][33];
    int z = blockIdx.z; int b = z >> 4, h = z & 15;
    int m0 = blockIdx.y * 32, d0 = blockIdx.x * 32;
    int x = threadIdx.x, y = threadIdx.y;
    const float* src = kv + (long long)b * 4096 + h * 256 + 128 + d0 + x;
    #pragma unroll
    for (int dy = 0; dy < 32; dy += 8)
        t[y + dy][x] = src[(long long)(m0 + y + dy) * 8192];
    __syncthreads();
    float* dst = vT + ((long long)z * 128 + d0) * 2048 + m0;
    #pragma unroll
    for (int dy = 0; dy < 32; dy += 8)
        dst[(long long)(y + dy) * 2048 + x] = t[x][y + dy];
}

// round-copy (for mem_hidden)
__global__ void rcopy_k(const float* __restrict__ in, float* __restrict__ out)
{
    long long i = (((long long)blockIdx.x * 256) + threadIdx.x) * 4;
    float4 v = *(const float4*)(in + i);
    v.x = rnd_tf32(v.x); v.y = rnd_tf32(v.y);
    v.z = rnd_tf32(v.z); v.w = rnd_tf32(v.w);
    *(float4*)(out + i) = v;
}

// ---------------- LayerNorm (tf32-rounded output) ----------------
__global__ void __launch_bounds__(256)
ln_k(const float* __restrict__ X, const float* __restrict__ gg,
     const float* __restrict__ bb, float* __restrict__ Y)
{
    __shared__ float sh[8];
    long long base = (long long)blockIdx.x * CH;
    int c0 = threadIdx.x * 8;
    float v[8];
    *(float4*)(v)     = *(const float4*)(X + base + c0);
    *(float4*)(v + 4) = *(const float4*)(X + base + c0 + 4);
    float s = 0.f;
    #pragma unroll
    for (int i = 0; i < 8; i++) s += v[i];
    s = block_sum(s, sh);
    float mu = s * (1.0f / CH);
    float d[8], s2 = 0.f;
    #pragma unroll
    for (int i = 0; i < 8; i++) { d[i] = v[i] - mu; s2 += d[i] * d[i]; }
    s2 = block_sum(s2, sh);
    float rstd = rsqrtf(s2 * (1.0f / CH) + 1e-5f);
    float o[8];
    #pragma unroll
    for (int i = 0; i < 8; i++) o[i] = rnd_tf32(d[i] * rstd * gg[c0 + i] + bb[c0 + i]);
    *(float4*)(Y + base + c0)     = *(float4*)(o);
    *(float4*)(Y + base + c0 + 4) = *(float4*)(o + 4);
}

// ---------------- L2 normalize 128-chunks (tf32-rounded) ----------------
__global__ void __launch_bounds__(256)
l2_k(float* __restrict__ X)
{
    long long chunk = (long long)blockIdx.x * 8 + (threadIdx.x >> 5);
    int lane = threadIdx.x & 31;
    float4* p = (float4*)(X + chunk * 128) + lane;
    float4 v = *p;
    float s = v.x * v.x + v.y * v.y + v.z * v.z + v.w * v.w;
    #pragma unroll
    for (int o = 16; o > 0; o >>= 1) s += __shfl_xor_sync(0xffffffffu, s, o);
    float r = rsqrtf(s + 1e-12f);
    v.x = rnd_tf32(v.x * r); v.y = rnd_tf32(v.y * r);
    v.z = rnd_tf32(v.z * r); v.w = rnd_tf32(v.w * r);
    *p = v;
}

// ---------------- masked softmax (tf32-rounded output) ----------------
__global__ void __launch_bounds__(256)
softmax_k(float* __restrict__ Sc, const void* __restrict__ maskp)
{
    __shared__ float sh[8];
    int r = blockIdx.x;
    int z = r >> 11, s = r & 2047;
    int b = z >> 4;
    float* row = Sc + (long long)r * CMM;
    long long moff = ((long long)b * CS + s) * CMM;
    int mode = g_mask_mode;
    int c0 = threadIdx.x * 8;

    float v[8];
    *(float4*)(v)     = *(float4*)(row + c0);
    *(float4*)(v + 4) = *(float4*)(row + c0 + 4);

    if (mode == 0) {
        const unsigned char* mp = (const unsigned char*)maskp + moff + c0;
        #pragma unroll
        for (int i = 0; i < 8; i++) if (mp[i]) v[i] = -1e4f;
    } else if (mode == 1) {
        const int* mp = (const int*)maskp + moff + c0;
        #pragma unroll
        for (int i = 0; i < 8; i++) if (mp[i]) v[i] = -1e4f;
    } else {
        const float* mp = (const float*)maskp + moff + c0;
        #pragma unroll
        for (int i = 0; i < 8; i++) if (mp[i] != 0.0f) v[i] = -1e4f;
    }

    float mx = -3.4e38f;
    #pragma unroll
    for (int i = 0; i < 8; i++) mx = fmaxf(mx, v[i]);
    mx = block_max(mx, sh);
    float e[8], sum = 0.f;
    #pragma unroll
    for (int i = 0; i < 8; i++) { e[i] = __expf(v[i] - mx); sum += e[i]; }
    sum = block_sum(sum, sh);
    float inv = 1.0f / sum;
    float o[8];
    #pragma unroll
    for (int i = 0; i < 8; i++) o[i] = rnd_tf32(e[i] * inv);
    *(float4*)(row + c0)     = *(float4*)(o);
    *(float4*)(row + c0 + 4) = *(float4*)(o + 4);
}

// ---------------- launcher ----------------
extern "C" void kernel_launch(void* const* d_in, const int* in_sizes, int n_in,
                              void* d_out, int out_size)
{
    const float* x    = (const float*)d_in[0];
    const float* memh = (const float*)d_in[1];
    const void*  mask = d_in[2];
    const float* ln1g = (const float*)d_in[3];
    const float* ln1b = (const float*)d_in[4];
    const float* ln2g = (const float*)d_in[5];
    const float* ln2b = (const float*)d_in[6];
    const float* ln3g = (const float*)d_in[7];
    const float* ln3b = (const float*)d_in[8];
    const float* w1i  = (const float*)d_in[9];
    const float* b1i  = (const float*)d_in[10];
    const float* w1o  = (const float*)d_in[11];
    const float* b1o  = (const float*)d_in[12];
    const float* wq   = (const float*)d_in[13];
    const float* bq   = (const float*)d_in[14];
    const float* wkv  = (const float*)d_in[15];
    const float* bkv  = (const float*)d_in[16];
    const float* wd   = (const float*)d_in[17];
    const float* bd   = (const float*)d_in[18];
    const float* w2i  = (const float*)d_in[19];
    const float* b2i  = (const float*)d_in[20];
    const float* w2o  = (const float*)d_in[21];
    const float* b2o  = (const float*)d_in[22];
    float* out = (float*)d_out;

    float *lnb, *hid, *x1, *q, *kv, *sc, *ctx, *x2, *memr;
    float *w1iT, *w1oT, *wqT, *wkvT, *wdT, *w2iT, *w2oT, *vT;
    cudaGetSymbolAddress((void**)&lnb,  g_ln);
    cudaGetSymbolAddress((void**)&hid,  g_hidden);
    cudaGetSymbolAddress((void**)&x1,   g_x1);
    cudaGetSymbolAddress((void**)&q,    g_q);
    cudaGetSymbolAddress((void**)&kv,   g_kv);
    cudaGetSymbolAddress((void**)&sc,   g_scores);
    cudaGetSymbolAddress((void**)&ctx,  g_ctx);
    cudaGetSymbolAddress((void**)&x2,   g_x2);
    cudaGetSymbolAddress((void**)&memr, g_memr);
    cudaGetSymbolAddress((void**)&w1iT, g_w1iT);
    cudaGetSymbolAddress((void**)&w1oT, g_w1oT);
    cudaGetSymbolAddress((void**)&wqT,  g_wqT);
    cudaGetSymbolAddress((void**)&wkvT, g_wkvT);
    cudaGetSymbolAddress((void**)&wdT,  g_wdT);
    cudaGetSymbolAddress((void**)&w2iT, g_w2iT);
    cudaGetSymbolAddress((void**)&w2oT, g_w2oT);
    cudaGetSymbolAddress((void**)&vT,   g_vT);

    cudaFuncSetAttribute(mgemm_k<true,  true >, cudaFuncAttributeMaxDynamicSharedMemorySize, SMEMB);
    cudaFuncSetAttribute(mgemm_k<false, false>, cudaFuncAttributeMaxDynamicSharedMemorySize, SMEMB);
    cudaFuncSetAttribute(mgemm_k<false, true >, cudaFuncAttributeMaxDynamicSharedMemorySize, SMEMB);

    dim3 tb(32, 8);

    detect_mask_k<<<1, 256>>>((const unsigned int*)mask);

    // weight transposes (+ tf32 rounding) and mem_hidden round-copy
    transpose_k<<<dim3(CFF/32, CH/32), tb>>>(w1i, w1iT, CH, CFF);
    transpose_k<<<dim3(CH/32, CFF/32), tb>>>(w1o, w1oT, CFF, CH);
    transpose_k<<<dim3(CH/32, CH/32),  tb>>>(wq,  wqT,  CH, CH);
    transpose_k<<<dim3(2*CH/32, CH/32),tb>>>(wkv, wkvT, CH, 2*CH);
    transpose_k<<<dim3(CH/32, CH/32),  tb>>>(wd,  wdT,  CH, CH);
    transpose_k<<<dim3(CFF/32, CH/32), tb>>>(w2i, w2iT, CH, CFF);
    transpose_k<<<dim3(CH/32, CFF/32), tb>>>(w2o, w2oT, CFF, CH);
    rcopy_k<<<(CR * CH) / 1024, 256>>>(memh, memr);

    // x = mlp1(ln1(x))
    ln_k<<<CR, 256>>>(x, ln1g, ln1b, lnb);
    mgemm_k<true, true><<<dim3(CFF/128, CR/128, 1), 256, SMEMB>>>(
        lnb, w1iT, hid, CH, CH, CH, CFF, 0, 0, 0, b1i, nullptr, 0, 1.0f);
    mgemm_k<false, false><<<dim3(CH/128, CR/128, 1), 256, SMEMB>>>(
        hid, w1oT, x1, CFF, CFF, CFF, CH, 0, 0, 0, b1o, nullptr, 0, 1.0f);

    // memory attention
    ln_k<<<CR, 256>>>(x1, ln2g, ln2b, lnb);
    mgemm_k<false, false><<<dim3(CH/128, CR/128, 1), 256, SMEMB>>>(
        lnb, wqT, q, CH, CH, CH, CH, 0, 0, 0, bq, nullptr, 0, 1.0f);
    l2_k<<<CR * CH / 1024, 256>>>(q);

    mgemm_k<false, false><<<dim3(2*CH/128, CR/128, 1), 256, SMEMB>>>(
        memr, wkvT, kv, CH, CH, CH, 2*CH, 0, 0, 0, bkv, nullptr, 0, 1.0f);
    l2_k<<<CR * 2 * CH / 1024, 256>>>(kv);
    vtrans_k<<<dim3(CD/32, CMM/32, NBATCH), tb>>>(kv, vT);

    // scores = (q . k) / sqrt(D), batched over z = b*16+h
    mgemm_k<false, false><<<dim3(CMM/128, CS/128, NBATCH), 256, SMEMB>>>(
        q, kv, sc, CD, 2*CH, 2*2*CH, CMM,
        128, 256, (long long)CS * CMM, nullptr, nullptr, 0, INV_NORM);

    softmax_k<<<NBATCH * CS, 256>>>(sc, mask);

    // ctx = probs @ v  via vT (NT form)
    mgemm_k<false, true><<<dim3(CD/128, CS/128, NBATCH), 256, SMEMB>>>(
        sc, vT, ctx, CMM, CMM, CMM, 2*CH,
        (long long)CS * CMM, (long long)CD * CMM, 128, nullptr, nullptr, 0, 1.0f);

    // x2 = x1 + ctx @ w_dense + b_dense
    mgemm_k<false, false><<<dim3(CH/128, CR/128, 1), 256, SMEMB>>>(
        ctx, wdT, x2, CH, CH, CH, CH, 0, 0, 0, bd, x1, CH, 1.0f);

    // out = x2 + mlp2(ln3(x2))
    ln_k<<<CR, 256>>>(x2, ln3g, ln3b, lnb);
    mgemm_k<true, true><<<dim3(CFF/128, CR/128, 1), 256, SMEMB>>>(
        lnb, w2iT, hid, CH, CH, CH, CFF, 0, 0, 0, b2i, nullptr, 0, 1.0f);
    mgemm_k<false, false><<<dim3(CH/128, CR/128, 1), 256, SMEMB>>>(
        hid, w2oT, out, CFF, CFF, CFF, CH, 0, 0, 0, b2o, x2, CH, 1.0f);
}

// round 7
// speedup vs baseline: 3.4872x; 1.2208x over previous
#include <cuda_runtime.h>
#include <cstdint>
#include <math.h>

// ---------------- problem constants ----------------
#define CH   2048
#define CFF  8192
#define CR   4096
#define CS   2048
#define CMM  2048
#define CD   128
#define NBATCH 32
#define INV_NORM 0.08838834764831843f

#define NSTG 3
#define LDSW 40                      // smem row stride (floats); (LDSW/2)%16==4 -> conflict-free LDS.64
#define AFL  (256 * LDSW)            // A-tile floats per stage
#define BFL  (128 * LDSW)            // B-tile floats per stage
#define STGF (AFL + BFL)
#define SMEMB (NSTG * STGF * 4)      // 184320 bytes

// ---------------- device scratch ----------------
__device__ float g_ln    [CR * CH];
__device__ float g_hidden[CR * CFF];
__device__ float g_x1    [CR * CH];
__device__ float g_q     [CR * CH];
__device__ float g_kv    [CR * 2 * CH];
__device__ float g_scores[(long long)NBATCH * CS * CMM];
__device__ float g_ctx   [CR * CH];
__device__ float g_x2    [CR * CH];
__device__ float g_memr  [CR * CH];
__device__ float g_w1iT  [CFF * CH];
__device__ float g_w1oT  [CH * CFF];
__device__ float g_wqT   [CH * CH];
__device__ float g_wkvT  [2 * CH * CH];
__device__ float g_wdT   [CH * CH];
__device__ float g_w2iT  [CFF * CH];
__device__ float g_w2oT  [CH * CFF];
__device__ float g_vT    [(long long)NBATCH * CD * CMM];
__device__ int   g_mask_mode;

// ---------------- helpers ----------------
__device__ __forceinline__ float rnd_tf32(float x) {
    uint32_t u;
    asm("cvt.rna.tf32.f32 %0, %1;" : "=r"(u) : "f"(x));
    return __uint_as_float(u);
}
__device__ __forceinline__ float gelu_f(float x) {
    float x3 = x * x * x;
    float t = tanhf(0.7978845608028654f * (x + 0.044715f * x3));
    return 0.5f * x * (1.0f + t);
}
__device__ __forceinline__ uint32_t smem_u32(const void* p) {
    uint32_t a;
    asm("{ .reg .u64 t; cvta.to.shared.u64 t, %1; cvt.u32.u64 %0, t; }" : "=r"(a) : "l"(p));
    return a;
}

__device__ __forceinline__ float block_sum(float v, float* sh) {
    #pragma unroll
    for (int o = 16; o > 0; o >>= 1) v += __shfl_xor_sync(0xffffffffu, v, o);
    int w = threadIdx.x >> 5;
    if ((threadIdx.x & 31) == 0) sh[w] = v;
    __syncthreads();
    if (w == 0) {
        float r = (threadIdx.x < 8) ? sh[threadIdx.x] : 0.0f;
        #pragma unroll
        for (int o = 4; o > 0; o >>= 1) r += __shfl_xor_sync(0xffffffffu, r, o);
        if (threadIdx.x == 0) sh[0] = r;
    }
    __syncthreads();
    float r = sh[0]; __syncthreads(); return r;
}
__device__ __forceinline__ float block_max(float v, float* sh) {
    #pragma unroll
    for (int o = 16; o > 0; o >>= 1) v = fmaxf(v, __shfl_xor_sync(0xffffffffu, v, o));
    int w = threadIdx.x >> 5;
    if ((threadIdx.x & 31) == 0) sh[w] = v;
    __syncthreads();
    if (w == 0) {
        float r = (threadIdx.x < 8) ? sh[threadIdx.x] : -3.4e38f;
        #pragma unroll
        for (int o = 4; o > 0; o >>= 1) r = fmaxf(r, __shfl_xor_sync(0xffffffffu, r, o));
        if (threadIdx.x == 0) sh[0] = r;
    }
    __syncthreads();
    float r = sh[0]; __syncthreads(); return r;
}

// ---------------- mask dtype detector ----------------
__global__ void detect_mask_k(const unsigned int* __restrict__ m) {
    __shared__ int sF, sB;
    if (threadIdx.x == 0) { sF = 0; sB = 0; }
    __syncthreads();
    for (int i = threadIdx.x; i < 2048; i += 256) {
        unsigned v = m[i];
        if (v == 0x3F800000u) sF = 1;
        else if (v > 1u) sB = 1;
    }
    __syncthreads();
    if (threadIdx.x == 0) g_mask_mode = sF ? 2 : (sB ? 0 : 1);
}

// ---------------- tf32 mma.sync GEMM (NT form) ----------------
// C[m,n] = f(alpha * sum_k A[m,k]*B[n,k] + bias[n]) (+ resid).
// CTA tile 256x128x32, 3-stage cp.async, 8 warps each 64(M)x64(N).
// Fragments read as LDS.64 via k-column reorder [0,2,4,6,1,3,5,7] per 8-col group
// (valid because k-summation is order-invariant; A and B use the same map).
template<bool GELU, bool ROUND>
__global__ void __launch_bounds__(256, 1)
mgemm_k(const float* __restrict__ Ag, const float* __restrict__ Bg,
        float* __restrict__ Cg, int K, int lda, int ldb, int ldc,
        long long bsA, long long bsB, long long bsC,
        const float* __restrict__ bias, const float* __restrict__ resid,
        int ldr, float alpha)
{
    extern __shared__ float sm[];
    const int tid = threadIdx.x, lane = tid & 31, wid = tid >> 5;
    const int m0 = blockIdx.y * 256, n0 = blockIdx.x * 128;
    const int wm = (wid & 3) * 64, wn = (wid >> 2) * 64;

    const float* A = Ag + (long long)blockIdx.z * bsA;
    const float* B = Bg + (long long)blockIdx.z * bsB;
    float*       C = Cg + (long long)blockIdx.z * bsC;

    // loader setup: 3072 16B-chunks per stage (A:2048, B:1024), 12 per thread
    const float* srcp[12];
    uint32_t dsto[12];
    const uint32_t sbase = smem_u32(sm);
    #pragma unroll
    for (int j = 0; j < 12; j++) {
        int g = tid + 256 * j;
        int isB = (g >= 2048);
        int gg = g - (isB ? 2048 : 0);
        int row = gg >> 3, kc = (gg & 7) * 4;
        srcp[j] = (isB ? B + (long long)(n0 + row) * ldb
                       : A + (long long)(m0 + row) * lda) + kc;
        dsto[j] = sbase + (uint32_t)(((isB ? AFL : 0) + row * LDSW + kc) * 4);
    }

    const int KT = K >> 5;

    #define ISSUE(IT, SG) do { \
        uint32_t stoff = (uint32_t)(SG) * (STGF * 4); \
        long long koff = (long long)(IT) * 32; \
        _Pragma("unroll") \
        for (int j = 0; j < 12; j++) { \
            asm volatile("cp.async.cg.shared.global [%0], [%1], 16;" \
                :: "r"(dsto[j] + stoff), "l"(srcp[j] + koff)); \
        } \
        asm volatile("cp.async.commit_group;" ::: "memory"); \
    } while (0)

    ISSUE(0, 0);
    ISSUE(1, 1);

    float acc[4][8][4];
    #pragma unroll
    for (int mt = 0; mt < 4; mt++)
        #pragma unroll
        for (int nt = 0; nt < 8; nt++)
            #pragma unroll
            for (int j = 0; j < 4; j++) acc[mt][nt][j] = 0.0f;

    const int r4 = lane >> 2, c4 = lane & 3;

    for (int it = 0; it < KT; it++) {
        int sg = it % NSTG;
        asm volatile("cp.async.wait_group 1;" ::: "memory");
        __syncthreads();
        if (it + 2 < KT) { ISSUE(it + 2, (it + 2) % NSTG); }
        else { asm volatile("cp.async.commit_group;" ::: "memory"); }

        const float* as_ = sm + sg * STGF;
        const float* bs_ = as_ + AFL;
        #pragma unroll
        for (int ks = 0; ks < 4; ks++) {
            int kp = ks * 8 + 2 * c4;     // physical col pair {2c4, 2c4+1} = positions {c4, c4+4}
            float2 al[4], ah[4], bb[8];
            #pragma unroll
            for (int mt = 0; mt < 4; mt++) {
                int rr = wm + mt * 16 + r4;
                al[mt] = *(const float2*)&as_[rr * LDSW + kp];
                ah[mt] = *(const float2*)&as_[(rr + 8) * LDSW + kp];
            }
            #pragma unroll
            for (int nt = 0; nt < 8; nt++) {
                int rn = wn + nt * 8 + r4;
                bb[nt] = *(const float2*)&bs_[rn * LDSW + kp];
            }
            #pragma unroll
            for (int mt = 0; mt < 4; mt++)
                #pragma unroll
                for (int nt = 0; nt < 8; nt++) {
                    asm volatile(
                        "mma.sync.aligned.m16n8k8.row.col.f32.tf32.tf32.f32 "
                        "{%0,%1,%2,%3}, {%4,%5,%6,%7}, {%8,%9}, {%0,%1,%2,%3};"
                        : "+f"(acc[mt][nt][0]), "+f"(acc[mt][nt][1]),
                          "+f"(acc[mt][nt][2]), "+f"(acc[mt][nt][3])
                        : "r"(__float_as_uint(al[mt].x)), "r"(__float_as_uint(ah[mt].x)),
                          "r"(__float_as_uint(al[mt].y)), "r"(__float_as_uint(ah[mt].y)),
                          "r"(__float_as_uint(bb[nt].x)), "r"(__float_as_uint(bb[nt].y)));
                }
        }
    }

    // ---- epilogue ----
    #pragma unroll
    for (int mt = 0; mt < 4; mt++) {
        #pragma unroll
        for (int h = 0; h < 2; h++) {
            int rr = m0 + wm + mt * 16 + h * 8 + r4;
            long long rbase = (long long)rr * ldc;
            long long robase = resid ? ((long long)rr * ldr) : 0;
            #pragma unroll
            for (int nt = 0; nt < 8; nt++) {
                int col = n0 + wn + nt * 8 + c4 * 2;
                float v0 = acc[mt][nt][h * 2 + 0] * alpha;
                float v1 = acc[mt][nt][h * 2 + 1] * alpha;
                if (bias) { v0 += bias[col]; v1 += bias[col + 1]; }
                if (GELU) { v0 = gelu_f(v0); v1 = gelu_f(v1); }
                if (resid) { v0 += resid[robase + col]; v1 += resid[robase + col + 1]; }
                if (ROUND) { v0 = rnd_tf32(v0); v1 = rnd_tf32(v1); }
                *(float2*)(C + rbase + col) = make_float2(v0, v1);
            }
        }
    }
    #undef ISSUE
}

// ---------------- transpose (+ tf32 round) ----------------
__global__ void transpose_k(const float* __restrict__ in, float* __restrict__ out,
                            int R, int Cc)
{
    __shared__ float t[32][33];
    int c0 = blockIdx.x * 32, r0 = blockIdx.y * 32;
    int x = threadIdx.x, y = threadIdx.y;
    #pragma unroll
    for (int dy = 0; dy < 32; dy += 8)
        t[y + dy][x] = in[(long long)(r0 + y + dy) * Cc + c0 + x];
    __syncthreads();
    #pragma unroll
    for (int dy = 0; dy < 32; dy += 8)
        out[(long long)(c0 + y + dy) * R + r0 + x] = rnd_tf32(t[x][y + dy]);
}

// vT[z][d][m] = v(m, z, d) from kv layout
__global__ void vtrans_k(const float* __restrict__ kv, float* __restrict__ vT)
{
    __shared__ float t[32][33];
    int z = blockIdx.z; int b = z >> 4, h = z & 15;
    int m0 = blockIdx.y * 32, d0 = blockIdx.x * 32;
    int x = threadIdx.x, y = threadIdx.y;
    const float* src = kv + (long long)b * 4096 + h * 256 + 128 + d0 + x;
    #pragma unroll
    for (int dy = 0; dy < 32; dy += 8)
        t[y + dy][x] = src[(long long)(m0 + y + dy) * 8192];
    __syncthreads();
    float* dst = vT + ((long long)z * 128 + d0) * 2048 + m0;
    #pragma unroll
    for (int dy = 0; dy < 32; dy += 8)
        dst[(long long)(y + dy) * 2048 + x] = t[x][y + dy];
}

// round-copy (for mem_hidden)
__global__ void rcopy_k(const float* __restrict__ in, float* __restrict__ out)
{
    long long i = (((long long)blockIdx.x * 256) + threadIdx.x) * 4;
    float4 v = *(const float4*)(in + i);
    v.x = rnd_tf32(v.x); v.y = rnd_tf32(v.y);
    v.z = rnd_tf32(v.z); v.w = rnd_tf32(v.w);
    *(float4*)(out + i) = v;
}

// ---------------- LayerNorm (tf32-rounded output) ----------------
__global__ void __launch_bounds__(256)
ln_k(const float* __restrict__ X, const float* __restrict__ gg,
     const float* __restrict__ bb, float* __restrict__ Y)
{
    __shared__ float sh[8];
    long long base = (long long)blockIdx.x * CH;
    int c0 = threadIdx.x * 8;
    float v[8];
    *(float4*)(v)     = *(const float4*)(X + base + c0);
    *(float4*)(v + 4) = *(const float4*)(X + base + c0 + 4);
    float s = 0.f;
    #pragma unroll
    for (int i = 0; i < 8; i++) s += v[i];
    s = block_sum(s, sh);
    float mu = s * (1.0f / CH);
    float d[8], s2 = 0.f;
    #pragma unroll
    for (int i = 0; i < 8; i++) { d[i] = v[i] - mu; s2 += d[i] * d[i]; }
    s2 = block_sum(s2, sh);
    float rstd = rsqrtf(s2 * (1.0f / CH) + 1e-5f);
    float o[8];
    #pragma unroll
    for (int i = 0; i < 8; i++) o[i] = rnd_tf32(d[i] * rstd * gg[c0 + i] + bb[c0 + i]);
    *(float4*)(Y + base + c0)     = *(float4*)(o);
    *(float4*)(Y + base + c0 + 4) = *(float4*)(o + 4);
}

// ---------------- L2 normalize 128-chunks (tf32-rounded) ----------------
__global__ void __launch_bounds__(256)
l2_k(float* __restrict__ X)
{
    long long chunk = (long long)blockIdx.x * 8 + (threadIdx.x >> 5);
    int lane = threadIdx.x & 31;
    float4* p = (float4*)(X + chunk * 128) + lane;
    float4 v = *p;
    float s = v.x * v.x + v.y * v.y + v.z * v.z + v.w * v.w;
    #pragma unroll
    for (int o = 16; o > 0; o >>= 1) s += __shfl_xor_sync(0xffffffffu, s, o);
    float r = rsqrtf(s + 1e-12f);
    v.x = rnd_tf32(v.x * r); v.y = rnd_tf32(v.y * r);
    v.z = rnd_tf32(v.z * r); v.w = rnd_tf32(v.w * r);
    *p = v;
}

// ---------------- masked softmax (tf32-rounded output) ----------------
__global__ void __launch_bounds__(256)
softmax_k(float* __restrict__ Sc, const void* __restrict__ maskp)
{
    __shared__ float sh[8];
    int r = blockIdx.x;
    int z = r >> 11, s = r & 2047;
    int b = z >> 4;
    float* row = Sc + (long long)r * CMM;
    long long moff = ((long long)b * CS + s) * CMM;
    int mode = g_mask_mode;
    int c0 = threadIdx.x * 8;

    float v[8];
    *(float4*)(v)     = *(float4*)(row + c0);
    *(float4*)(v + 4) = *(float4*)(row + c0 + 4);

    if (mode == 0) {
        const unsigned char* mp = (const unsigned char*)maskp + moff + c0;
        #pragma unroll
        for (int i = 0; i < 8; i++) if (mp[i]) v[i] = -1e4f;
    } else if (mode == 1) {
        const int* mp = (const int*)maskp + moff + c0;
        #pragma unroll
        for (int i = 0; i < 8; i++) if (mp[i]) v[i] = -1e4f;
    } else {
        const float* mp = (const float*)maskp + moff + c0;
        #pragma unroll
        for (int i = 0; i < 8; i++) if (mp[i] != 0.0f) v[i] = -1e4f;
    }

    float mx = -3.4e38f;
    #pragma unroll
    for (int i = 0; i < 8; i++) mx = fmaxf(mx, v[i]);
    mx = block_max(mx, sh);
    float e[8], sum = 0.f;
    #pragma unroll
    for (int i = 0; i < 8; i++) { e[i] = __expf(v[i] - mx); sum += e[i]; }
    sum = block_sum(sum, sh);
    float inv = 1.0f / sum;
    float o[8];
    #pragma unroll
    for (int i = 0; i < 8; i++) o[i] = rnd_tf32(e[i] * inv);
    *(float4*)(row + c0)     = *(float4*)(o);
    *(float4*)(row + c0 + 4) = *(float4*)(o + 4);
}

// ---------------- launcher ----------------
extern "C" void kernel_launch(void* const* d_in, const int* in_sizes, int n_in,
                              void* d_out, int out_size)
{
    const float* x    = (const float*)d_in[0];
    const float* memh = (const float*)d_in[1];
    const void*  mask = d_in[2];
    const float* ln1g = (const float*)d_in[3];
    const float* ln1b = (const float*)d_in[4];
    const float* ln2g = (const float*)d_in[5];
    const float* ln2b = (const float*)d_in[6];
    const float* ln3g = (const float*)d_in[7];
    const float* ln3b = (const float*)d_in[8];
    const float* w1i  = (const float*)d_in[9];
    const float* b1i  = (const float*)d_in[10];
    const float* w1o  = (const float*)d_in[11];
    const float* b1o  = (const float*)d_in[12];
    const float* wq   = (const float*)d_in[13];
    const float* bq   = (const float*)d_in[14];
    const float* wkv  = (const float*)d_in[15];
    const float* bkv  = (const float*)d_in[16];
    const float* wd   = (const float*)d_in[17];
    const float* bd   = (const float*)d_in[18];
    const float* w2i  = (const float*)d_in[19];
    const float* b2i  = (const float*)d_in[20];
    const float* w2o  = (const float*)d_in[21];
    const float* b2o  = (const float*)d_in[22];
    float* out = (float*)d_out;

    float *lnb, *hid, *x1, *q, *kv, *sc, *ctx, *x2, *memr;
    float *w1iT, *w1oT, *wqT, *wkvT, *wdT, *w2iT, *w2oT, *vT;
    cudaGetSymbolAddress((void**)&lnb,  g_ln);
    cudaGetSymbolAddress((void**)&hid,  g_hidden);
    cudaGetSymbolAddress((void**)&x1,   g_x1);
    cudaGetSymbolAddress((void**)&q,    g_q);
    cudaGetSymbolAddress((void**)&kv,   g_kv);
    cudaGetSymbolAddress((void**)&sc,   g_scores);
    cudaGetSymbolAddress((void**)&ctx,  g_ctx);
    cudaGetSymbolAddress((void**)&x2,   g_x2);
    cudaGetSymbolAddress((void**)&memr, g_memr);
    cudaGetSymbolAddress((void**)&w1iT, g_w1iT);
    cudaGetSymbolAddress((void**)&w1oT, g_w1oT);
    cudaGetSymbolAddress((void**)&wqT,  g_wqT);
    cudaGetSymbolAddress((void**)&wkvT, g_wkvT);
    cudaGetSymbolAddress((void**)&wdT,  g_wdT);
    cudaGetSymbolAddress((void**)&w2iT, g_w2iT);
    cudaGetSymbolAddress((void**)&w2oT, g_w2oT);
    cudaGetSymbolAddress((void**)&vT,   g_vT);

    cudaFuncSetAttribute(mgemm_k<true,  true >, cudaFuncAttributeMaxDynamicSharedMemorySize, SMEMB);
    cudaFuncSetAttribute(mgemm_k<false, false>, cudaFuncAttributeMaxDynamicSharedMemorySize, SMEMB);
    cudaFuncSetAttribute(mgemm_k<false, true >, cudaFuncAttributeMaxDynamicSharedMemorySize, SMEMB);

    dim3 tb(32, 8);

    detect_mask_k<<<1, 256>>>((const unsigned int*)mask);

    // weight transposes (+ tf32 rounding) and mem_hidden round-copy
    transpose_k<<<dim3(CFF/32, CH/32), tb>>>(w1i, w1iT, CH, CFF);
    transpose_k<<<dim3(CH/32, CFF/32), tb>>>(w1o, w1oT, CFF, CH);
    transpose_k<<<dim3(CH/32, CH/32),  tb>>>(wq,  wqT,  CH, CH);
    transpose_k<<<dim3(2*CH/32, CH/32),tb>>>(wkv, wkvT, CH, 2*CH);
    transpose_k<<<dim3(CH/32, CH/32),  tb>>>(wd,  wdT,  CH, CH);
    transpose_k<<<dim3(CFF/32, CH/32), tb>>>(w2i, w2iT, CH, CFF);
    transpose_k<<<dim3(CH/32, CFF/32), tb>>>(w2o, w2oT, CFF, CH);
    rcopy_k<<<(CR * CH) / 1024, 256>>>(memh, memr);

    // x = mlp1(ln1(x))
    ln_k<<<CR, 256>>>(x, ln1g, ln1b, lnb);
    mgemm_k<true, true><<<dim3(CFF/128, CR/256, 1), 256, SMEMB>>>(
        lnb, w1iT, hid, CH, CH, CH, CFF, 0, 0, 0, b1i, nullptr, 0, 1.0f);
    mgemm_k<false, false><<<dim3(CH/128, CR/256, 1), 256, SMEMB>>>(
        hid, w1oT, x1, CFF, CFF, CFF, CH, 0, 0, 0, b1o, nullptr, 0, 1.0f);

    // memory attention
    ln_k<<<CR, 256>>>(x1, ln2g, ln2b, lnb);
    mgemm_k<false, false><<<dim3(CH/128, CR/256, 1), 256, SMEMB>>>(
        lnb, wqT, q, CH, CH, CH, CH, 0, 0, 0, bq, nullptr, 0, 1.0f);
    l2_k<<<CR * CH / 1024, 256>>>(q);

    mgemm_k<false, false><<<dim3(2*CH/128, CR/256, 1), 256, SMEMB>>>(
        memr, wkvT, kv, CH, CH, CH, 2*CH, 0, 0, 0, bkv, nullptr, 0, 1.0f);
    l2_k<<<CR * 2 * CH / 1024, 256>>>(kv);
    vtrans_k<<<dim3(CD/32, CMM/32, NBATCH), tb>>>(kv, vT);

    // scores = (q . k) / sqrt(D), batched over z = b*16+h
    mgemm_k<false, false><<<dim3(CMM/128, CS/256, NBATCH), 256, SMEMB>>>(
        q, kv, sc, CD, 2*CH, 2*2*CH, CMM,
        128, 256, (long long)CS * CMM, nullptr, nullptr, 0, INV_NORM);

    softmax_k<<<NBATCH * CS, 256>>>(sc, mask);

    // ctx = probs @ v  via vT (NT form)
    mgemm_k<false, true><<<dim3(CD/128, CS/256, NBATCH), 256, SMEMB>>>(
        sc, vT, ctx, CMM, CMM, CMM, 2*CH,
        (long long)CS * CMM, (long long)CD * CMM, 128, nullptr, nullptr, 0, 1.0f);

    // x2 = x1 + ctx @ w_dense + b_dense
    mgemm_k<false, false><<<dim3(CH/128, CR/256, 1), 256, SMEMB>>>(
        ctx, wdT, x2, CH, CH, CH, CH, 0, 0, 0, bd, x1, CH, 1.0f);

    // out = x2 + mlp2(ln3(x2))
    ln_k<<<CR, 256>>>(x2, ln3g, ln3b, lnb);
    mgemm_k<true, true><<<dim3(CFF/128, CR/256, 1), 256, SMEMB>>>(
        lnb, w2iT, hid, CH, CH, CH, CFF, 0, 0, 0, b2i, nullptr, 0, 1.0f);
    mgemm_k<false, false><<<dim3(CH/128, CR/256, 1), 256, SMEMB>>>(
        hid, w2oT, out, CFF, CFF, CFF, CH, 0, 0, 0, b2o, x2, CH, 1.0f);
}

// round 8
// speedup vs baseline: 3.4907x; 1.0010x over previous
#include <cuda_runtime.h>
#include <cstdint>
#include <math.h>

// ---------------- problem constants ----------------
#define CH   2048
#define CFF  8192
#define CR   4096
#define CS   2048
#define CMM  2048
#define CD   128
#define NBATCH 32
#define INV_NORM 0.08838834764831843f

#define NSTG 3
#define LDSW 40                      // smem row stride (floats); (LDSW/2)%16==4 -> conflict-free LDS.64
#define AFL  (256 * LDSW)            // A-tile floats per stage
#define BFL  (128 * LDSW)            // B-tile floats per stage
#define STGF (AFL + BFL)
#define SMEMB (NSTG * STGF * 4)      // 184320 bytes

// ---------------- device scratch ----------------
__device__ float g_ln    [CR * CH];
__device__ float g_hidden[CR * CFF];
__device__ float g_x1    [CR * CH];
__device__ float g_q     [CR * CH];
__device__ float g_kv    [CR * 2 * CH];
__device__ float g_scores[(long long)NBATCH * CS * CMM];
__device__ float g_ctx   [CR * CH];
__device__ float g_x2    [CR * CH];
__device__ float g_memr  [CR * CH];
__device__ float g_w1iT  [CFF * CH];
__device__ float g_w1oT  [CH * CFF];
__device__ float g_wqT   [CH * CH];
__device__ float g_wkvT  [2 * CH * CH];
__device__ float g_wdT   [CH * CH];
__device__ float g_w2iT  [CFF * CH];
__device__ float g_w2oT  [CH * CFF];
__device__ float g_vT    [(long long)NBATCH * CD * CMM];
__device__ int   g_mask_mode;

// ---------------- helpers ----------------
__device__ __forceinline__ float rnd_tf32(float x) {
    uint32_t u;
    asm("cvt.rna.tf32.f32 %0, %1;" : "=r"(u) : "f"(x));
    return __uint_as_float(u);
}
__device__ __forceinline__ float gelu_f(float x) {
    float x3 = x * x * x;
    float t = tanhf(0.7978845608028654f * (x + 0.044715f * x3));
    return 0.5f * x * (1.0f + t);
}
__device__ __forceinline__ uint32_t smem_u32(const void* p) {
    uint32_t a;
    asm("{ .reg .u64 t; cvta.to.shared.u64 t, %1; cvt.u32.u64 %0, t; }" : "=r"(a) : "l"(p));
    return a;
}

__device__ __forceinline__ float block_sum(float v, float* sh) {
    #pragma unroll
    for (int o = 16; o > 0; o >>= 1) v += __shfl_xor_sync(0xffffffffu, v, o);
    int w = threadIdx.x >> 5;
    if ((threadIdx.x & 31) == 0) sh[w] = v;
    __syncthreads();
    if (w == 0) {
        float r = (threadIdx.x < 8) ? sh[threadIdx.x] : 0.0f;
        #pragma unroll
        for (int o = 4; o > 0; o >>= 1) r += __shfl_xor_sync(0xffffffffu, r, o);
        if (threadIdx.x == 0) sh[0] = r;
    }
    __syncthreads();
    float r = sh[0]; __syncthreads(); return r;
}
__device__ __forceinline__ float block_max(float v, float* sh) {
    #pragma unroll
    for (int o = 16; o > 0; o >>= 1) v = fmaxf(v, __shfl_xor_sync(0xffffffffu, v, o));
    int w = threadIdx.x >> 5;
    if ((threadIdx.x & 31) == 0) sh[w] = v;
    __syncthreads();
    if (w == 0) {
        float r = (threadIdx.x < 8) ? sh[threadIdx.x] : -3.4e38f;
        #pragma unroll
        for (int o = 4; o > 0; o >>= 1) r = fmaxf(r, __shfl_xor_sync(0xffffffffu, r, o));
        if (threadIdx.x == 0) sh[0] = r;
    }
    __syncthreads();
    float r = sh[0]; __syncthreads(); return r;
}

// ---------------- mask dtype detector ----------------
__global__ void detect_mask_k(const unsigned int* __restrict__ m) {
    __shared__ int sF, sB;
    if (threadIdx.x == 0) { sF = 0; sB = 0; }
    __syncthreads();
    for (int i = threadIdx.x; i < 2048; i += 256) {
        unsigned v = m[i];
        if (v == 0x3F800000u) sF = 1;
        else if (v > 1u) sB = 1;
    }
    __syncthreads();
    if (threadIdx.x == 0) g_mask_mode = sF ? 2 : (sB ? 0 : 1);
}

// ---------------- tf32 mma.sync GEMM (NT form) ----------------
// C[m,n] = f(alpha * sum_k A[m,k]*B[n,k] + bias[n]) (+ resid).
// CTA tile 256x128x32, 3-stage cp.async, 8 warps each 64(M)x64(N).
// L2-aware rasterization: CTAs remapped into 8-wide n super-groups so a
// wave reuses A from L2 and streams each B tile exactly once.
template<bool GELU, bool ROUND>
__global__ void __launch_bounds__(256, 1)
mgemm_k(const float* __restrict__ Ag, const float* __restrict__ Bg,
        float* __restrict__ Cg, int K, int lda, int ldb, int ldc,
        long long bsA, long long bsB, long long bsC,
        const float* __restrict__ bias, const float* __restrict__ resid,
        int ldr, float alpha)
{
    extern __shared__ float sm[];
    const int tid = threadIdx.x, lane = tid & 31, wid = tid >> 5;

    // ---- swizzled rasterization ----
    const int NX = gridDim.x, NY = gridDim.y;
    int lid = blockIdx.y * NX + blockIdx.x;
    int per = 8 * NY;
    int g   = lid / per, r_ = lid - g * per;
    int gw  = NX - g * 8; if (gw > 8) gw = 8;
    const int m0 = (r_ / gw) * 256;
    const int n0 = (g * 8 + (r_ % gw)) * 128;

    const int wm = (wid & 3) * 64, wn = (wid >> 2) * 64;

    const float* A = Ag + (long long)blockIdx.z * bsA;
    const float* B = Bg + (long long)blockIdx.z * bsB;
    float*       C = Cg + (long long)blockIdx.z * bsC;

    // loader setup: 3072 16B-chunks per stage (A:2048, B:1024), 12 per thread
    const float* srcp[12];
    uint32_t dsto[12];
    const uint32_t sbase = smem_u32(sm);
    #pragma unroll
    for (int j = 0; j < 12; j++) {
        int gg0 = tid + 256 * j;
        int isB = (gg0 >= 2048);
        int gg = gg0 - (isB ? 2048 : 0);
        int row = gg >> 3, kc = (gg & 7) * 4;
        srcp[j] = (isB ? B + (long long)(n0 + row) * ldb
                       : A + (long long)(m0 + row) * lda) + kc;
        dsto[j] = sbase + (uint32_t)(((isB ? AFL : 0) + row * LDSW + kc) * 4);
    }

    const int KT = K >> 5;

    #define ISSUE(IT, SG) do { \
        uint32_t stoff = (uint32_t)(SG) * (STGF * 4); \
        long long koff = (long long)(IT) * 32; \
        _Pragma("unroll") \
        for (int j = 0; j < 12; j++) { \
            asm volatile("cp.async.cg.shared.global [%0], [%1], 16;" \
                :: "r"(dsto[j] + stoff), "l"(srcp[j] + koff)); \
        } \
        asm volatile("cp.async.commit_group;" ::: "memory"); \
    } while (0)

    ISSUE(0, 0);
    ISSUE(1, 1);

    float acc[4][8][4];
    #pragma unroll
    for (int mt = 0; mt < 4; mt++)
        #pragma unroll
        for (int nt = 0; nt < 8; nt++)
            #pragma unroll
            for (int j = 0; j < 4; j++) acc[mt][nt][j] = 0.0f;

    const int r4 = lane >> 2, c4 = lane & 3;

    for (int it = 0; it < KT; it++) {
        int sg = it % NSTG;
        asm volatile("cp.async.wait_group 1;" ::: "memory");
        __syncthreads();
        if (it + 2 < KT) { ISSUE(it + 2, (it + 2) % NSTG); }
        else { asm volatile("cp.async.commit_group;" ::: "memory"); }

        const float* as_ = sm + sg * STGF;
        const float* bs_ = as_ + AFL;
        #pragma unroll
        for (int ks = 0; ks < 4; ks++) {
            int kp = ks * 8 + 2 * c4;     // physical col pair {2c4, 2c4+1} = positions {c4, c4+4}
            float2 al[4], ah[4], bb[8];
            #pragma unroll
            for (int mt = 0; mt < 4; mt++) {
                int rr = wm + mt * 16 + r4;
                al[mt] = *(const float2*)&as_[rr * LDSW + kp];
                ah[mt] = *(const float2*)&as_[(rr + 8) * LDSW + kp];
            }
            #pragma unroll
            for (int nt = 0; nt < 8; nt++) {
                int rn = wn + nt * 8 + r4;
                bb[nt] = *(const float2*)&bs_[rn * LDSW + kp];
            }
            #pragma unroll
            for (int mt = 0; mt < 4; mt++)
                #pragma unroll
                for (int nt = 0; nt < 8; nt++) {
                    asm volatile(
                        "mma.sync.aligned.m16n8k8.row.col.f32.tf32.tf32.f32 "
                        "{%0,%1,%2,%3}, {%4,%5,%6,%7}, {%8,%9}, {%0,%1,%2,%3};"
                        : "+f"(acc[mt][nt][0]), "+f"(acc[mt][nt][1]),
                          "+f"(acc[mt][nt][2]), "+f"(acc[mt][nt][3])
                        : "r"(__float_as_uint(al[mt].x)), "r"(__float_as_uint(ah[mt].x)),
                          "r"(__float_as_uint(al[mt].y)), "r"(__float_as_uint(ah[mt].y)),
                          "r"(__float_as_uint(bb[nt].x)), "r"(__float_as_uint(bb[nt].y)));
                }
        }
    }

    // ---- epilogue ----
    #pragma unroll
    for (int mt = 0; mt < 4; mt++) {
        #pragma unroll
        for (int h = 0; h < 2; h++) {
            int rr = m0 + wm + mt * 16 + h * 8 + r4;
            long long rbase = (long long)rr * ldc;
            long long robase = resid ? ((long long)rr * ldr) : 0;
            #pragma unroll
            for (int nt = 0; nt < 8; nt++) {
                int col = n0 + wn + nt * 8 + c4 * 2;
                float v0 = acc[mt][nt][h * 2 + 0] * alpha;
                float v1 = acc[mt][nt][h * 2 + 1] * alpha;
                if (bias) { v0 += bias[col]; v1 += bias[col + 1]; }
                if (GELU) { v0 = gelu_f(v0); v1 = gelu_f(v1); }
                if (resid) { v0 += resid[robase + col]; v1 += resid[robase + col + 1]; }
                if (ROUND) { v0 = rnd_tf32(v0); v1 = rnd_tf32(v1); }
                *(float2*)(C + rbase + col) = make_float2(v0, v1);
            }
        }
    }
    #undef ISSUE
}

// ---------------- transpose (+ tf32 round) ----------------
__global__ void transpose_k(const float* __restrict__ in, float* __restrict__ out,
                            int R, int Cc)
{
    __shared__ float t[32][33];
    int c0 = blockIdx.x * 32, r0 = blockIdx.y * 32;
    int x = threadIdx.x, y = threadIdx.y;
    #pragma unroll
    for (int dy = 0; dy < 32; dy += 8)
        t[y + dy][x] = in[(long long)(r0 + y + dy) * Cc + c0 + x];
    __syncthreads();
    #pragma unroll
    for (int dy = 0; dy < 32; dy += 8)
        out[(long long)(c0 + y + dy) * R + r0 + x] = rnd_tf32(t[x][y + dy]);
}

// vT[z][d][m] = v(m, z, d) from kv layout
__global__ void vtrans_k(const float* __restrict__ kv, float* __restrict__ vT)
{
    __shared__ float t[32][33];
    int z = blockIdx.z; int b = z >> 4, h = z & 15;
    int m0 = blockIdx.y * 32, d0 = blockIdx.x * 32;
    int x = threadIdx.x, y = threadIdx.y;
    const float* src = kv + (long long)b * 4096 + h * 256 + 128 + d0 + x;
    #pragma unroll
    for (int dy = 0; dy < 32; dy += 8)
        t[y + dy][x] = src[(long long)(m0 + y + dy) * 8192];
    __syncthreads();
    float* dst = vT + ((long long)z * 128 + d0) * 2048 + m0;
    #pragma unroll
    for (int dy = 0; dy < 32; dy += 8)
        dst[(long long)(y + dy) * 2048 + x] = t[x][y + dy];
}

// round-copy (for mem_hidden)
__global__ void rcopy_k(const float* __restrict__ in, float* __restrict__ out)
{
    long long i = (((long long)blockIdx.x * 256) + threadIdx.x) * 4;
    float4 v = *(const float4*)(in + i);
    v.x = rnd_tf32(v.x); v.y = rnd_tf32(v.y);
    v.z = rnd_tf32(v.z); v.w = rnd_tf32(v.w);
    *(float4*)(out + i) = v;
}

// ---------------- LayerNorm (tf32-rounded output) ----------------
__global__ void __launch_bounds__(256)
ln_k(const float* __restrict__ X, const float* __restrict__ gg,
     const float* __restrict__ bb, float* __restrict__ Y)
{
    __shared__ float sh[8];
    long long base = (long long)blockIdx.x * CH;
    int c0 = threadIdx.x * 8;
    float v[8];
    *(float4*)(v)     = *(const float4*)(X + base + c0);
    *(float4*)(v + 4) = *(const float4*)(X + base + c0 + 4);
    float s = 0.f;
    #pragma unroll
    for (int i = 0; i < 8; i++) s += v[i];
    s = block_sum(s, sh);
    float mu = s * (1.0f / CH);
    float d[8], s2 = 0.f;
    #pragma unroll
    for (int i = 0; i < 8; i++) { d[i] = v[i] - mu; s2 += d[i] * d[i]; }
    s2 = block_sum(s2, sh);
    float rstd = rsqrtf(s2 * (1.0f / CH) + 1e-5f);
    float o[8];
    #pragma unroll
    for (int i = 0; i < 8; i++) o[i] = rnd_tf32(d[i] * rstd * gg[c0 + i] + bb[c0 + i]);
    *(float4*)(Y + base + c0)     = *(float4*)(o);
    *(float4*)(Y + base + c0 + 4) = *(float4*)(o + 4);
}

// ---------------- L2 normalize 128-chunks (tf32-rounded) ----------------
__global__ void __launch_bounds__(256)
l2_k(float* __restrict__ X)
{
    long long chunk = (long long)blockIdx.x * 8 + (threadIdx.x >> 5);
    int lane = threadIdx.x & 31;
    float4* p = (float4*)(X + chunk * 128) + lane;
    float4 v = *p;
    float s = v.x * v.x + v.y * v.y + v.z * v.z + v.w * v.w;
    #pragma unroll
    for (int o = 16; o > 0; o >>= 1) s += __shfl_xor_sync(0xffffffffu, s, o);
    float r = rsqrtf(s + 1e-12f);
    v.x = rnd_tf32(v.x * r); v.y = rnd_tf32(v.y * r);
    v.z = rnd_tf32(v.z * r); v.w = rnd_tf32(v.w * r);
    *p = v;
}

// ---------------- masked softmax (tf32-rounded output) ----------------
__global__ void __launch_bounds__(256)
softmax_k(float* __restrict__ Sc, const void* __restrict__ maskp)
{
    __shared__ float sh[8];
    int r = blockIdx.x;
    int z = r >> 11, s = r & 2047;
    int b = z >> 4;
    float* row = Sc + (long long)r * CMM;
    long long moff = ((long long)b * CS + s) * CMM;
    int mode = g_mask_mode;
    int c0 = threadIdx.x * 8;

    float v[8];
    *(float4*)(v)     = *(float4*)(row + c0);
    *(float4*)(v + 4) = *(float4*)(row + c0 + 4);

    if (mode == 0) {
        const unsigned char* mp = (const unsigned char*)maskp + moff + c0;
        #pragma unroll
        for (int i = 0; i < 8; i++) if (mp[i]) v[i] = -1e4f;
    } else if (mode == 1) {
        const int* mp = (const int*)maskp + moff + c0;
        #pragma unroll
        for (int i = 0; i < 8; i++) if (mp[i]) v[i] = -1e4f;
    } else {
        const float* mp = (const float*)maskp + moff + c0;
        #pragma unroll
        for (int i = 0; i < 8; i++) if (mp[i] != 0.0f) v[i] = -1e4f;
    }

    float mx = -3.4e38f;
    #pragma unroll
    for (int i = 0; i < 8; i++) mx = fmaxf(mx, v[i]);
    mx = block_max(mx, sh);
    float e[8], sum = 0.f;
    #pragma unroll
    for (int i = 0; i < 8; i++) { e[i] = __expf(v[i] - mx); sum += e[i]; }
    sum = block_sum(sum, sh);
    float inv = 1.0f / sum;
    float o[8];
    #pragma unroll
    for (int i = 0; i < 8; i++) o[i] = rnd_tf32(e[i] * inv);
    *(float4*)(row + c0)     = *(float4*)(o);
    *(float4*)(row + c0 + 4) = *(float4*)(o + 4);
}

// ---------------- launcher ----------------
extern "C" void kernel_launch(void* const* d_in, const int* in_sizes, int n_in,
                              void* d_out, int out_size)
{
    const float* x    = (const float*)d_in[0];
    const float* memh = (const float*)d_in[1];
    const void*  mask = d_in[2];
    const float* ln1g = (const float*)d_in[3];
    const float* ln1b = (const float*)d_in[4];
    const float* ln2g = (const float*)d_in[5];
    const float* ln2b = (const float*)d_in[6];
    const float* ln3g = (const float*)d_in[7];
    const float* ln3b = (const float*)d_in[8];
    const float* w1i  = (const float*)d_in[9];
    const float* b1i  = (const float*)d_in[10];
    const float* w1o  = (const float*)d_in[11];
    const float* b1o  = (const float*)d_in[12];
    const float* wq   = (const float*)d_in[13];
    const float* bq   = (const float*)d_in[14];
    const float* wkv  = (const float*)d_in[15];
    const float* bkv  = (const float*)d_in[16];
    const float* wd   = (const float*)d_in[17];
    const float* bd   = (const float*)d_in[18];
    const float* w2i  = (const float*)d_in[19];
    const float* b2i  = (const float*)d_in[20];
    const float* w2o  = (const float*)d_in[21];
    const float* b2o  = (const float*)d_in[22];
    float* out = (float*)d_out;

    float *lnb, *hid, *x1, *q, *kv, *sc, *ctx, *x2, *memr;
    float *w1iT, *w1oT, *wqT, *wkvT, *wdT, *w2iT, *w2oT, *vT;
    cudaGetSymbolAddress((void**)&lnb,  g_ln);
    cudaGetSymbolAddress((void**)&hid,  g_hidden);
    cudaGetSymbolAddress((void**)&x1,   g_x1);
    cudaGetSymbolAddress((void**)&q,    g_q);
    cudaGetSymbolAddress((void**)&kv,   g_kv);
    cudaGetSymbolAddress((void**)&sc,   g_scores);
    cudaGetSymbolAddress((void**)&ctx,  g_ctx);
    cudaGetSymbolAddress((void**)&x2,   g_x2);
    cudaGetSymbolAddress((void**)&memr, g_memr);
    cudaGetSymbolAddress((void**)&w1iT, g_w1iT);
    cudaGetSymbolAddress((void**)&w1oT, g_w1oT);
    cudaGetSymbolAddress((void**)&wqT,  g_wqT);
    cudaGetSymbolAddress((void**)&wkvT, g_wkvT);
    cudaGetSymbolAddress((void**)&wdT,  g_wdT);
    cudaGetSymbolAddress((void**)&w2iT, g_w2iT);
    cudaGetSymbolAddress((void**)&w2oT, g_w2oT);
    cudaGetSymbolAddress((void**)&vT,   g_vT);

    cudaFuncSetAttribute(mgemm_k<true,  true >, cudaFuncAttributeMaxDynamicSharedMemorySize, SMEMB);
    cudaFuncSetAttribute(mgemm_k<false, false>, cudaFuncAttributeMaxDynamicSharedMemorySize, SMEMB);
    cudaFuncSetAttribute(mgemm_k<false, true >, cudaFuncAttributeMaxDynamicSharedMemorySize, SMEMB);

    dim3 tb(32, 8);

    detect_mask_k<<<1, 256>>>((const unsigned int*)mask);

    // weight transposes (+ tf32 rounding) and mem_hidden round-copy
    transpose_k<<<dim3(CFF/32, CH/32), tb>>>(w1i, w1iT, CH, CFF);
    transpose_k<<<dim3(CH/32, CFF/32), tb>>>(w1o, w1oT, CFF, CH);
    transpose_k<<<dim3(CH/32, CH/32),  tb>>>(wq,  wqT,  CH, CH);
    transpose_k<<<dim3(2*CH/32, CH/32),tb>>>(wkv, wkvT, CH, 2*CH);
    transpose_k<<<dim3(CH/32, CH/32),  tb>>>(wd,  wdT,  CH, CH);
    transpose_k<<<dim3(CFF/32, CH/32), tb>>>(w2i, w2iT, CH, CFF);
    transpose_k<<<dim3(CH/32, CFF/32), tb>>>(w2o, w2oT, CFF, CH);
    rcopy_k<<<(CR * CH) / 1024, 256>>>(memh, memr);

    // x = mlp1(ln1(x))
    ln_k<<<CR, 256>>>(x, ln1g, ln1b, lnb);
    mgemm_k<true, true><<<dim3(CFF/128, CR/256, 1), 256, SMEMB>>>(
        lnb, w1iT, hid, CH, CH, CH, CFF, 0, 0, 0, b1i, nullptr, 0, 1.0f);
    mgemm_k<false, false><<<dim3(CH/128, CR/256, 1), 256, SMEMB>>>(
        hid, w1oT, x1, CFF, CFF, CFF, CH, 0, 0, 0, b1o, nullptr, 0, 1.0f);

    // memory attention
    ln_k<<<CR, 256>>>(x1, ln2g, ln2b, lnb);
    mgemm_k<false, false><<<dim3(CH/128, CR/256, 1), 256, SMEMB>>>(
        lnb, wqT, q, CH, CH, CH, CH, 0, 0, 0, bq, nullptr, 0, 1.0f);
    l2_k<<<CR * CH / 1024, 256>>>(q);

    mgemm_k<false, false><<<dim3(2*CH/128, CR/256, 1), 256, SMEMB>>>(
        memr, wkvT, kv, CH, CH, CH, 2*CH, 0, 0, 0, bkv, nullptr, 0, 1.0f);
    l2_k<<<CR * 2 * CH / 1024, 256>>>(kv);
    vtrans_k<<<dim3(CD/32, CMM/32, NBATCH), tb>>>(kv, vT);

    // scores = (q . k) / sqrt(D), batched over z = b*16+h
    mgemm_k<false, false><<<dim3(CMM/128, CS/256, NBATCH), 256, SMEMB>>>(
        q, kv, sc, CD, 2*CH, 2*2*CH, CMM,
        128, 256, (long long)CS * CMM, nullptr, nullptr, 0, INV_NORM);

    softmax_k<<<NBATCH * CS, 256>>>(sc, mask);

    // ctx = probs @ v  via vT (NT form)
    mgemm_k<false, true><<<dim3(CD/128, CS/256, NBATCH), 256, SMEMB>>>(
        sc, vT, ctx, CMM, CMM, CMM, 2*CH,
        (long long)CS * CMM, (long long)CD * CMM, 128, nullptr, nullptr, 0, 1.0f);

    // x2 = x1 + ctx @ w_dense + b_dense
    mgemm_k<false, false><<<dim3(CH/128, CR/256, 1), 256, SMEMB>>>(
        ctx, wdT, x2, CH, CH, CH, CH, 0, 0, 0, bd, x1, CH, 1.0f);

    // out = x2 + mlp2(ln3(x2))
    ln_k<<<CR, 256>>>(x2, ln3g, ln3b, lnb);
    mgemm_k<true, true><<<dim3(CFF/128, CR/256, 1), 256, SMEMB>>>(
        lnb, w2iT, hid, CH, CH, CH, CFF, 0, 0, 0, b2i, nullptr, 0, 1.0f);
    mgemm_k<false, false><<<dim3(CH/128, CR/256, 1), 256, SMEMB>>>(
        hid, w2oT, out, CFF, CFF, CFF, CH, 0, 0, 0, b2o, x2, CH, 1.0f);
}

// round 9
// speedup vs baseline: 6.2371x; 1.7868x over previous
#include <cuda_runtime.h>
#include <cuda_fp16.h>
#include <cstdint>
#include <math.h>

// ---------------- problem constants ----------------
#define CH   2048
#define CFF  8192
#define CR   4096
#define CS   2048
#define CMM  2048
#define CD   128
#define NBATCH 32
#define INV_NORM 0.08838834764831843f

#define NSTG 3
#define KTIL 64                       // k per stage (halves)
#define LDSWH 80                      // halves per smem row (160B): conflict-free LDS.64
#define AFLH (256 * LDSWH)            // A-tile halves per stage
#define BFLH (128 * LDSWH)            // B-tile halves per stage
#define STGH (AFLH + BFLH)            // halves per stage
#define SMEMB (NSTG * STGH * 2)       // 184320 bytes

// ---------------- device scratch ----------------
__device__ __half g_lnh [CR * CH];
__device__ __half g_hid [CR * CFF];
__device__ float  g_x1  [CR * CH];
__device__ float  g_qf  [CR * CH];
__device__ __half g_qh  [CR * CH];
__device__ float  g_kvf [CR * 2 * CH];
__device__ __half g_kvh [CR * 2 * CH];
__device__ __half g_sch [(long long)NBATCH * CS * CMM];
__device__ __half g_ctxh[CR * CH];
__device__ float  g_x2  [CR * CH];
__device__ __half g_memh[CR * CH];
__device__ __half g_w1iT[CFF * CH];
__device__ __half g_w1oT[CH * CFF];
__device__ __half g_wqT [CH * CH];
__device__ __half g_wkvT[2 * CH * CH];
__device__ __half g_wdT [CH * CH];
__device__ __half g_w2iT[CFF * CH];
__device__ __half g_w2oT[CH * CFF];
__device__ __half g_vT  [(long long)NBATCH * CD * CMM];
__device__ int    g_mask_mode;

// ---------------- helpers ----------------
__device__ __forceinline__ float gelu_f(float x) {
    float x3 = x * x * x;
    float t = tanhf(0.7978845608028654f * (x + 0.044715f * x3));
    return 0.5f * x * (1.0f + t);
}
__device__ __forceinline__ uint32_t smem_u32(const void* p) {
    uint32_t a;
    asm("{ .reg .u64 t; cvta.to.shared.u64 t, %1; cvt.u32.u64 %0, t; }" : "=r"(a) : "l"(p));
    return a;
}

__device__ __forceinline__ float block_sum(float v, float* sh) {
    #pragma unroll
    for (int o = 16; o > 0; o >>= 1) v += __shfl_xor_sync(0xffffffffu, v, o);
    int w = threadIdx.x >> 5;
    if ((threadIdx.x & 31) == 0) sh[w] = v;
    __syncthreads();
    if (w == 0) {
        float r = (threadIdx.x < 8) ? sh[threadIdx.x] : 0.0f;
        #pragma unroll
        for (int o = 4; o > 0; o >>= 1) r += __shfl_xor_sync(0xffffffffu, r, o);
        if (threadIdx.x == 0) sh[0] = r;
    }
    __syncthreads();
    float r = sh[0]; __syncthreads(); return r;
}
__device__ __forceinline__ float block_max(float v, float* sh) {
    #pragma unroll
    for (int o = 16; o > 0; o >>= 1) v = fmaxf(v, __shfl_xor_sync(0xffffffffu, v, o));
    int w = threadIdx.x >> 5;
    if ((threadIdx.x & 31) == 0) sh[w] = v;
    __syncthreads();
    if (w == 0) {
        float r = (threadIdx.x < 8) ? sh[threadIdx.x] : -3.4e38f;
        #pragma unroll
        for (int o = 4; o > 0; o >>= 1) r = fmaxf(r, __shfl_xor_sync(0xffffffffu, r, o));
        if (threadIdx.x == 0) sh[0] = r;
    }
    __syncthreads();
    float r = sh[0]; __syncthreads(); return r;
}

// ---------------- mask dtype detector ----------------
__global__ void detect_mask_k(const unsigned int* __restrict__ m) {
    __shared__ int sF, sB;
    if (threadIdx.x == 0) { sF = 0; sB = 0; }
    __syncthreads();
    for (int i = threadIdx.x; i < 2048; i += 256) {
        unsigned v = m[i];
        if (v == 0x3F800000u) sF = 1;
        else if (v > 1u) sB = 1;
    }
    __syncthreads();
    if (threadIdx.x == 0) g_mask_mode = sF ? 2 : (sB ? 0 : 1);
}

// ---------------- fp16 mma.sync GEMM (NT form) ----------------
// C[m,n] = f(alpha * sum_k A[m,k]*B[n,k] + bias[n]) (+ resid).
// CTA tile 256x128x64, 3-stage cp.async, 8 warps each 64(M)x64(N).
// mma.m16n8k16 f16 with f32 accumulate. Fragments via LDS.64 with
// k-position remap {4c4..4c4+3} -> {2c4,2c4+1,2c4+8,2c4+9} (bijective,
// same for A and B, so the k-summation is exactly preserved).
template<bool GELU, bool OUTH>
__global__ void __launch_bounds__(256, 1)
hgemm_k(const __half* __restrict__ Ag, const __half* __restrict__ Bg,
        void* __restrict__ Cg, int K, int lda, int ldb, int ldc,
        long long bsA, long long bsB, long long bsC,
        const float* __restrict__ bias, const float* __restrict__ resid,
        int ldr, float alpha)
{
    extern __shared__ __half smh[];
    const int tid = threadIdx.x, lane = tid & 31, wid = tid >> 5;

    // ---- swizzled rasterization (8-wide n super-groups) ----
    const int NX = gridDim.x, NY = gridDim.y;
    int lid = blockIdx.y * NX + blockIdx.x;
    int per = 8 * NY;
    int g   = lid / per, r_ = lid - g * per;
    int gw  = NX - g * 8; if (gw > 8) gw = 8;
    const int m0 = (r_ / gw) * 256;
    const int n0 = (g * 8 + (r_ % gw)) * 128;

    const int wm = (wid & 3) * 64, wn = (wid >> 2) * 64;

    const __half* A = Ag + (long long)blockIdx.z * bsA;
    const __half* B = Bg + (long long)blockIdx.z * bsB;

    // loader: 3072 16B granules per stage (A:2048, B:1024), 12 per thread
    const __half* srcp[12];
    uint32_t dsto[12];
    const uint32_t sbase = smem_u32(smh);
    #pragma unroll
    for (int j = 0; j < 12; j++) {
        int gg0 = tid + 256 * j;
        int isB = (gg0 >= 2048);
        int gg = gg0 - (isB ? 2048 : 0);
        int row = gg >> 3, kg = (gg & 7) * 8;          // 8 halves per granule
        srcp[j] = (isB ? B + (long long)(n0 + row) * ldb
                       : A + (long long)(m0 + row) * lda) + kg;
        dsto[j] = sbase + (uint32_t)(((isB ? AFLH : 0) + row * LDSWH + kg) * 2);
    }

    const int KT = K / KTIL;

    #define ISSUE(IT, SG) do { \
        uint32_t stoff = (uint32_t)(SG) * (STGH * 2); \
        long long koff = (long long)(IT) * KTIL; \
        _Pragma("unroll") \
        for (int j = 0; j < 12; j++) { \
            asm volatile("cp.async.cg.shared.global [%0], [%1], 16;" \
                :: "r"(dsto[j] + stoff), "l"(srcp[j] + koff)); \
        } \
        asm volatile("cp.async.commit_group;" ::: "memory"); \
    } while (0)

    ISSUE(0, 0);
    ISSUE(1, 1);

    float acc[4][8][4];
    #pragma unroll
    for (int mt = 0; mt < 4; mt++)
        #pragma unroll
        for (int nt = 0; nt < 8; nt++)
            #pragma unroll
            for (int j = 0; j < 4; j++) acc[mt][nt][j] = 0.0f;

    const int r4 = lane >> 2, c4 = lane & 3;

    for (int it = 0; it < KT; it++) {
        int sg = it % NSTG;
        asm volatile("cp.async.wait_group 1;" ::: "memory");
        __syncthreads();
        if (it + 2 < KT) { ISSUE(it + 2, (it + 2) % NSTG); }
        else { asm volatile("cp.async.commit_group;" ::: "memory"); }

        const __half* as_ = smh + sg * STGH;
        const __half* bs_ = as_ + AFLH;
        #pragma unroll
        for (int ks = 0; ks < 4; ks++) {
            int kbase = ks * 16 + 4 * c4;
            uint2 al[4], ah[4], bb[8];
            #pragma unroll
            for (int mt = 0; mt < 4; mt++) {
                int rr = wm + mt * 16 + r4;
                al[mt] = *(const uint2*)&as_[rr * LDSWH + kbase];
                ah[mt] = *(const uint2*)&as_[(rr + 8) * LDSWH + kbase];
            }
            #pragma unroll
            for (int nt = 0; nt < 8; nt++) {
                int rn = wn + nt * 8 + r4;
                bb[nt] = *(const uint2*)&bs_[rn * LDSWH + kbase];
            }
            #pragma unroll
            for (int mt = 0; mt < 4; mt++)
                #pragma unroll
                for (int nt = 0; nt < 8; nt++) {
                    asm volatile(
                        "mma.sync.aligned.m16n8k16.row.col.f32.f16.f16.f32 "
                        "{%0,%1,%2,%3}, {%4,%5,%6,%7}, {%8,%9}, {%0,%1,%2,%3};"
                        : "+f"(acc[mt][nt][0]), "+f"(acc[mt][nt][1]),
                          "+f"(acc[mt][nt][2]), "+f"(acc[mt][nt][3])
                        : "r"(al[mt].x), "r"(ah[mt].x), "r"(al[mt].y), "r"(ah[mt].y),
                          "r"(bb[nt].x), "r"(bb[nt].y));
                }
        }
    }

    // ---- epilogue ----
    #pragma unroll
    for (int mt = 0; mt < 4; mt++) {
        #pragma unroll
        for (int h = 0; h < 2; h++) {
            int rr = m0 + wm + mt * 16 + h * 8 + r4;
            long long rbase = (long long)rr * ldc;
            long long robase = resid ? ((long long)rr * ldr) : 0;
            #pragma unroll
            for (int nt = 0; nt < 8; nt++) {
                int col = n0 + wn + nt * 8 + c4 * 2;
                float v0 = acc[mt][nt][h * 2 + 0] * alpha;
                float v1 = acc[mt][nt][h * 2 + 1] * alpha;
                if (bias) { v0 += bias[col]; v1 += bias[col + 1]; }
                if (GELU) { v0 = gelu_f(v0); v1 = gelu_f(v1); }
                if (resid) { v0 += resid[robase + col]; v1 += resid[robase + col + 1]; }
                if (OUTH) {
                    __half2* C = (__half2*)((__half*)Cg + (long long)blockIdx.z * bsC + rbase + col);
                    *C = __floats2half2_rn(v0, v1);
                } else {
                    float* C = (float*)Cg + (long long)blockIdx.z * bsC + rbase + col;
                    *(float2*)C = make_float2(v0, v1);
                }
            }
        }
    }
    #undef ISSUE
}

// ---------------- transpose float -> half ----------------
__global__ void transpose_k(const float* __restrict__ in, __half* __restrict__ out,
                            int R, int Cc)
{
    __shared__ float t[32][33];
    int c0 = blockIdx.x * 32, r0 = blockIdx.y * 32;
    int x = threadIdx.x, y = threadIdx.y;
    #pragma unroll
    for (int dy = 0; dy < 32; dy += 8)
        t[y + dy][x] = in[(long long)(r0 + y + dy) * Cc + c0 + x];
    __syncthreads();
    #pragma unroll
    for (int dy = 0; dy < 32; dy += 8)
        out[(long long)(c0 + y + dy) * R + r0 + x] = __float2half(t[x][y + dy]);
}

// vT[z][d][m] = normalized v(m, z, d) from kvh layout (halves)
__global__ void vtrans_k(const __half* __restrict__ kvh, __half* __restrict__ vT)
{
    __shared__ __half t[32][40];
    int z = blockIdx.z; int b = z >> 4, h = z & 15;
    int m0 = blockIdx.y * 32, d0 = blockIdx.x * 32;
    int x = threadIdx.x, y = threadIdx.y;
    const __half* src = kvh + (long long)b * 4096 + h * 256 + 128 + d0 + x;
    #pragma unroll
    for (int dy = 0; dy < 32; dy += 8)
        t[y + dy][x] = src[(long long)(m0 + y + dy) * 8192];
    __syncthreads();
    __half* dst = vT + ((long long)z * 128 + d0) * 2048 + m0;
    #pragma unroll
    for (int dy = 0; dy < 32; dy += 8)
        dst[(long long)(y + dy) * 2048 + x] = t[x][y + dy];
}

// float -> half copy (mem_hidden)
__global__ void rcopy_k(const float* __restrict__ in, __half* __restrict__ out)
{
    long long i = (((long long)blockIdx.x * 256) + threadIdx.x) * 4;
    float4 v = *(const float4*)(in + i);
    __align__(8) __half2 o[2];
    o[0] = __floats2half2_rn(v.x, v.y);
    o[1] = __floats2half2_rn(v.z, v.w);
    *(uint2*)(out + i) = *(uint2*)o;
}

// ---------------- LayerNorm: float in, half out ----------------
__global__ void __launch_bounds__(256)
ln_k(const float* __restrict__ X, const float* __restrict__ gg,
     const float* __restrict__ bb, __half* __restrict__ Y)
{
    __shared__ float sh[8];
    long long base = (long long)blockIdx.x * CH;
    int c0 = threadIdx.x * 8;
    float v[8];
    *(float4*)(v)     = *(const float4*)(X + base + c0);
    *(float4*)(v + 4) = *(const float4*)(X + base + c0 + 4);
    float s = 0.f;
    #pragma unroll
    for (int i = 0; i < 8; i++) s += v[i];
    s = block_sum(s, sh);
    float mu = s * (1.0f / CH);
    float d[8], s2 = 0.f;
    #pragma unroll
    for (int i = 0; i < 8; i++) { d[i] = v[i] - mu; s2 += d[i] * d[i]; }
    s2 = block_sum(s2, sh);
    float rstd = rsqrtf(s2 * (1.0f / CH) + 1e-5f);
    __align__(16) __half2 o[4];
    #pragma unroll
    for (int i = 0; i < 4; i++) {
        float a = d[2*i]   * rstd * gg[c0 + 2*i]   + bb[c0 + 2*i];
        float b = d[2*i+1] * rstd * gg[c0 + 2*i+1] + bb[c0 + 2*i+1];
        o[i] = __floats2half2_rn(a, b);
    }
    *(uint4*)(Y + base + c0) = *(uint4*)o;
}

// ---------------- L2 normalize 128-chunks: float in, half out ----------------
__global__ void __launch_bounds__(256)
l2_k(const float* __restrict__ in, __half* __restrict__ out)
{
    long long chunk = (long long)blockIdx.x * 8 + (threadIdx.x >> 5);
    int lane = threadIdx.x & 31;
    const float4* p = (const float4*)(in + chunk * 128) + lane;
    float4 v = *p;
    float s = v.x * v.x + v.y * v.y + v.z * v.z + v.w * v.w;
    #pragma unroll
    for (int o = 16; o > 0; o >>= 1) s += __shfl_xor_sync(0xffffffffu, s, o);
    float r = rsqrtf(s + 1e-12f);
    __align__(8) __half2 o2[2];
    o2[0] = __floats2half2_rn(v.x * r, v.y * r);
    o2[1] = __floats2half2_rn(v.z * r, v.w * r);
    *(uint2*)(out + chunk * 128 + lane * 4) = *(uint2*)o2;
}

// ---------------- masked softmax over M=2048, half in/out (in-place) --------
__global__ void __launch_bounds__(256)
softmax_k(__half* __restrict__ Sc, const void* __restrict__ maskp)
{
    __shared__ float sh[8];
    int r = blockIdx.x;
    int z = r >> 11, s = r & 2047;
    int b = z >> 4;
    __half* row = Sc + (long long)r * CMM;
    long long moff = ((long long)b * CS + s) * CMM;
    int mode = g_mask_mode;
    int c0 = threadIdx.x * 8;

    __align__(16) __half2 hv[4];
    *(uint4*)hv = *(uint4*)(row + c0);
    float v[8];
    #pragma unroll
    for (int i = 0; i < 4; i++) {
        float2 f = __half22float2(hv[i]);
        v[2*i] = f.x; v[2*i+1] = f.y;
    }

    if (mode == 0) {
        const unsigned char* mp = (const unsigned char*)maskp + moff + c0;
        #pragma unroll
        for (int i = 0; i < 8; i++) if (mp[i]) v[i] = -1e4f;
    } else if (mode == 1) {
        const int* mp = (const int*)maskp + moff + c0;
        #pragma unroll
        for (int i = 0; i < 8; i++) if (mp[i]) v[i] = -1e4f;
    } else {
        const float* mp = (const float*)maskp + moff + c0;
        #pragma unroll
        for (int i = 0; i < 8; i++) if (mp[i] != 0.0f) v[i] = -1e4f;
    }

    float mx = -3.4e38f;
    #pragma unroll
    for (int i = 0; i < 8; i++) mx = fmaxf(mx, v[i]);
    mx = block_max(mx, sh);
    float e[8], sum = 0.f;
    #pragma unroll
    for (int i = 0; i < 8; i++) { e[i] = __expf(v[i] - mx); sum += e[i]; }
    sum = block_sum(sum, sh);
    float inv = 1.0f / sum;
    __align__(16) __half2 o[4];
    #pragma unroll
    for (int i = 0; i < 4; i++)
        o[i] = __floats2half2_rn(e[2*i] * inv, e[2*i+1] * inv);
    *(uint4*)(row + c0) = *(uint4*)o;
}

// ---------------- launcher ----------------
extern "C" void kernel_launch(void* const* d_in, const int* in_sizes, int n_in,
                              void* d_out, int out_size)
{
    const float* x    = (const float*)d_in[0];
    const float* memh = (const float*)d_in[1];
    const void*  mask = d_in[2];
    const float* ln1g = (const float*)d_in[3];
    const float* ln1b = (const float*)d_in[4];
    const float* ln2g = (const float*)d_in[5];
    const float* ln2b = (const float*)d_in[6];
    const float* ln3g = (const float*)d_in[7];
    const float* ln3b = (const float*)d_in[8];
    const float* w1i  = (const float*)d_in[9];
    const float* b1i  = (const float*)d_in[10];
    const float* w1o  = (const float*)d_in[11];
    const float* b1o  = (const float*)d_in[12];
    const float* wq   = (const float*)d_in[13];
    const float* bq   = (const float*)d_in[14];
    const float* wkv  = (const float*)d_in[15];
    const float* bkv  = (const float*)d_in[16];
    const float* wd   = (const float*)d_in[17];
    const float* bd   = (const float*)d_in[18];
    const float* w2i  = (const float*)d_in[19];
    const float* b2i  = (const float*)d_in[20];
    const float* w2o  = (const float*)d_in[21];
    const float* b2o  = (const float*)d_in[22];
    float* out = (float*)d_out;

    __half *lnh, *hid, *qh, *kvh, *sch, *ctxh, *memhh, *vT;
    __half *w1iT, *w1oT, *wqT, *wkvT, *wdT, *w2iT, *w2oT;
    float *x1, *qf, *kvf, *x2;
    cudaGetSymbolAddress((void**)&lnh,   g_lnh);
    cudaGetSymbolAddress((void**)&hid,   g_hid);
    cudaGetSymbolAddress((void**)&x1,    g_x1);
    cudaGetSymbolAddress((void**)&qf,    g_qf);
    cudaGetSymbolAddress((void**)&qh,    g_qh);
    cudaGetSymbolAddress((void**)&kvf,   g_kvf);
    cudaGetSymbolAddress((void**)&kvh,   g_kvh);
    cudaGetSymbolAddress((void**)&sch,   g_sch);
    cudaGetSymbolAddress((void**)&ctxh,  g_ctxh);
    cudaGetSymbolAddress((void**)&x2,    g_x2);
    cudaGetSymbolAddress((void**)&memhh, g_memh);
    cudaGetSymbolAddress((void**)&w1iT,  g_w1iT);
    cudaGetSymbolAddress((void**)&w1oT,  g_w1oT);
    cudaGetSymbolAddress((void**)&wqT,   g_wqT);
    cudaGetSymbolAddress((void**)&wkvT,  g_wkvT);
    cudaGetSymbolAddress((void**)&wdT,   g_wdT);
    cudaGetSymbolAddress((void**)&w2iT,  g_w2iT);
    cudaGetSymbolAddress((void**)&w2oT,  g_w2oT);
    cudaGetSymbolAddress((void**)&vT,    g_vT);

    cudaFuncSetAttribute(hgemm_k<true,  true >, cudaFuncAttributeMaxDynamicSharedMemorySize, SMEMB);
    cudaFuncSetAttribute(hgemm_k<false, false>, cudaFuncAttributeMaxDynamicSharedMemorySize, SMEMB);
    cudaFuncSetAttribute(hgemm_k<false, true >, cudaFuncAttributeMaxDynamicSharedMemorySize, SMEMB);

    dim3 tb(32, 8);

    detect_mask_k<<<1, 256>>>((const unsigned int*)mask);

    // weight transposes to half; mem_hidden cast to half
    transpose_k<<<dim3(CFF/32, CH/32), tb>>>(w1i, w1iT, CH, CFF);
    transpose_k<<<dim3(CH/32, CFF/32), tb>>>(w1o, w1oT, CFF, CH);
    transpose_k<<<dim3(CH/32, CH/32),  tb>>>(wq,  wqT,  CH, CH);
    transpose_k<<<dim3(2*CH/32, CH/32),tb>>>(wkv, wkvT, CH, 2*CH);
    transpose_k<<<dim3(CH/32, CH/32),  tb>>>(wd,  wdT,  CH, CH);
    transpose_k<<<dim3(CFF/32, CH/32), tb>>>(w2i, w2iT, CH, CFF);
    transpose_k<<<dim3(CH/32, CFF/32), tb>>>(w2o, w2oT, CFF, CH);
    rcopy_k<<<(CR * CH) / 1024, 256>>>(memh, memhh);

    // x = mlp1(ln1(x))
    ln_k<<<CR, 256>>>(x, ln1g, ln1b, lnh);
    hgemm_k<true, true><<<dim3(CFF/128, CR/256, 1), 256, SMEMB>>>(
        lnh, w1iT, hid, CH, CH, CH, CFF, 0, 0, 0, b1i, nullptr, 0, 1.0f);
    hgemm_k<false, false><<<dim3(CH/128, CR/256, 1), 256, SMEMB>>>(
        hid, w1oT, x1, CFF, CFF, CFF, CH, 0, 0, 0, b1o, nullptr, 0, 1.0f);

    // memory attention
    ln_k<<<CR, 256>>>(x1, ln2g, ln2b, lnh);
    hgemm_k<false, false><<<dim3(CH/128, CR/256, 1), 256, SMEMB>>>(
        lnh, wqT, qf, CH, CH, CH, CH, 0, 0, 0, bq, nullptr, 0, 1.0f);
    l2_k<<<CR * CH / 1024, 256>>>(qf, qh);

    hgemm_k<false, false><<<dim3(2*CH/128, CR/256, 1), 256, SMEMB>>>(
        memhh, wkvT, kvf, CH, CH, CH, 2*CH, 0, 0, 0, bkv, nullptr, 0, 1.0f);
    l2_k<<<CR * 2 * CH / 1024, 256>>>(kvf, kvh);
    vtrans_k<<<dim3(CD/32, CMM/32, NBATCH), tb>>>(kvh, vT);

    // scores = (q . k) / sqrt(D), half out, batched over z = b*16+h
    hgemm_k<false, true><<<dim3(CMM/128, CS/256, NBATCH), 256, SMEMB>>>(
        qh, kvh, sch, CD, 2*CH, 2*2*CH, CMM,
        128, 256, (long long)CS * CMM, nullptr, nullptr, 0, INV_NORM);

    softmax_k<<<NBATCH * CS, 256>>>(sch, mask);

    // ctx = probs @ v  via vT (NT form), half out, ctx stored [CR x CH] halves
    hgemm_k<false, true><<<dim3(CD/128, CS/256, NBATCH), 256, SMEMB>>>(
        sch, vT, ctxh, CMM, CMM, CMM, 2*CH,
        (long long)CS * CMM, (long long)CD * CMM, 128, nullptr, nullptr, 0, 1.0f);

    // x2 = x1 + ctx @ w_dense + b_dense
    hgemm_k<false, false><<<dim3(CH/128, CR/256, 1), 256, SMEMB>>>(
        ctxh, wdT, x2, CH, CH, CH, CH, 0, 0, 0, bd, x1, CH, 1.0f);

    // out = x2 + mlp2(ln3(x2))
    ln_k<<<CR, 256>>>(x2, ln3g, ln3b, lnh);
    hgemm_k<true, true><<<dim3(CFF/128, CR/256, 1), 256, SMEMB>>>(
        lnh, w2iT, hid, CH, CH, CH, CFF, 0, 0, 0, b2i, nullptr, 0, 1.0f);
    hgemm_k<false, false><<<dim3(CH/128, CR/256, 1), 256, SMEMB>>>(
        hid, w2oT, out, CFF, CFF, CFF, CH, 0, 0, 0, b2o, x2, CH, 1.0f);
}

// round 12
// speedup vs baseline: 6.2593x; 1.0036x over previous
#include <cuda_runtime.h>
#include <cuda_fp16.h>
#include <cstdint>
#include <math.h>

// ---------------- problem constants ----------------
#define CH   2048
#define CFF  8192
#define CR   4096
#define CS   2048
#define CMM  2048
#define CD   128
#define NBATCH 32
#define INV_NORM 0.08838834764831843f

#define NSTG 3
#define KTIL 64                       // k per stage (halves)
#define LDSWH 80                      // halves per smem row (160B): conflict-free LDS.64
#define AFLH (256 * LDSWH)
#define BFLH (128 * LDSWH)
#define STGH (AFLH + BFLH)
#define SMEMB (NSTG * STGH * 2)       // 184320 bytes

// ---------------- device scratch ----------------
__device__ __half g_lnh [CR * CH];
__device__ __half g_hid [CR * CFF];
__device__ float  g_x1  [CR * CH];
__device__ __half g_qh  [CR * CH];
__device__ __half g_kvh [CR * 2 * CH];
__device__ __half g_sch [(long long)NBATCH * CS * CMM];
__device__ __half g_ctxh[CR * CH];
__device__ float  g_x2  [CR * CH];
__device__ __half g_memh[CR * CH];
__device__ __half g_w1iT[CFF * CH];
__device__ __half g_w1oT[CH * CFF];
__device__ __half g_wqT [CH * CH];
__device__ __half g_wkvT[2 * CH * CH];
__device__ __half g_wdT [CH * CH];
__device__ __half g_w2iT[CFF * CH];
__device__ __half g_w2oT[CH * CFF];
__device__ __half g_vT  [(long long)NBATCH * CD * CMM];
__device__ int    g_mask_mode;

// ---------------- helpers ----------------
__device__ __forceinline__ float gelu_f(float x) {
    float x3 = x * x * x;
    float t = tanhf(0.7978845608028654f * (x + 0.044715f * x3));
    return 0.5f * x * (1.0f + t);
}
__device__ __forceinline__ uint32_t smem_u32(const void* p) {
    uint32_t a;
    asm("{ .reg .u64 t; cvta.to.shared.u64 t, %1; cvt.u32.u64 %0, t; }" : "=r"(a) : "l"(p));
    return a;
}

__device__ __forceinline__ float block_sum(float v, float* sh) {
    #pragma unroll
    for (int o = 16; o > 0; o >>= 1) v += __shfl_xor_sync(0xffffffffu, v, o);
    int w = threadIdx.x >> 5;
    if ((threadIdx.x & 31) == 0) sh[w] = v;
    __syncthreads();
    if (w == 0) {
        float r = (threadIdx.x < 8) ? sh[threadIdx.x] : 0.0f;
        #pragma unroll
        for (int o = 4; o > 0; o >>= 1) r += __shfl_xor_sync(0xffffffffu, r, o);
        if (threadIdx.x == 0) sh[0] = r;
    }
    __syncthreads();
    float r = sh[0]; __syncthreads(); return r;
}
__device__ __forceinline__ float block_max(float v, float* sh) {
    #pragma unroll
    for (int o = 16; o > 0; o >>= 1) v = fmaxf(v, __shfl_xor_sync(0xffffffffu, v, o));
    int w = threadIdx.x >> 5;
    if ((threadIdx.x & 31) == 0) sh[w] = v;
    __syncthreads();
    if (w == 0) {
        float r = (threadIdx.x < 8) ? sh[threadIdx.x] : -3.4e38f;
        #pragma unroll
        for (int o = 4; o > 0; o >>= 1) r = fmaxf(r, __shfl_xor_sync(0xffffffffu, r, o));
        if (threadIdx.x == 0) sh[0] = r;
    }
    __syncthreads();
    float r = sh[0]; __syncthreads(); return r;
}

// ---------------- mask dtype detector ----------------
__global__ void detect_mask_k(const unsigned int* __restrict__ m) {
    __shared__ int sF, sB;
    if (threadIdx.x == 0) { sF = 0; sB = 0; }
    __syncthreads();
    for (int i = threadIdx.x; i < 2048; i += 256) {
        unsigned v = m[i];
        if (v == 0x3F800000u) sF = 1;
        else if (v > 1u) sB = 1;
    }
    __syncthreads();
    if (threadIdx.x == 0) g_mask_mode = sF ? 2 : (sB ? 0 : 1);
}

// ---------------- fp16 mma.sync GEMM (NT form) ----------------
// C[m,n] = f(alpha * sum_k A[m,k]*B[n,k] + bias[n]) (+ resid).
// CTA tile 256x128x64, 3-stage cp.async, 8 warps each 64(M)x64(N).
template<bool GELU, bool OUTH>
__global__ void __launch_bounds__(256, 1)
hgemm_k(const __half* __restrict__ Ag, const __half* __restrict__ Bg,
        void* __restrict__ Cg, int K, int lda, int ldb, int ldc,
        long long bsA, long long bsB, long long bsC,
        const float* __restrict__ bias, const float* __restrict__ resid,
        int ldr, float alpha)
{
    extern __shared__ __half smh[];
    const int tid = threadIdx.x, lane = tid & 31, wid = tid >> 5;

    // swizzled rasterization (8-wide n super-groups)
    const int NX = gridDim.x, NY = gridDim.y;
    int lid = blockIdx.y * NX + blockIdx.x;
    int per = 8 * NY;
    int g   = lid / per, r_ = lid - g * per;
    int gw  = NX - g * 8; if (gw > 8) gw = 8;
    const int m0 = (r_ / gw) * 256;
    const int n0 = (g * 8 + (r_ % gw)) * 128;

    const int wm = (wid & 3) * 64, wn = (wid >> 2) * 64;

    const __half* A = Ag + (long long)blockIdx.z * bsA;
    const __half* B = Bg + (long long)blockIdx.z * bsB;

    const __half* srcp[12];
    uint32_t dsto[12];
    const uint32_t sbase = smem_u32(smh);
    #pragma unroll
    for (int j = 0; j < 12; j++) {
        int gg0 = tid + 256 * j;
        int isB = (gg0 >= 2048);
        int gg = gg0 - (isB ? 2048 : 0);
        int row = gg >> 3, kg = (gg & 7) * 8;
        srcp[j] = (isB ? B + (long long)(n0 + row) * ldb
                       : A + (long long)(m0 + row) * lda) + kg;
        dsto[j] = sbase + (uint32_t)(((isB ? AFLH : 0) + row * LDSWH + kg) * 2);
    }

    const int KT = K / KTIL;

    #define ISSUE(IT, SG) do { \
        uint32_t stoff = (uint32_t)(SG) * (STGH * 2); \
        long long koff = (long long)(IT) * KTIL; \
        _Pragma("unroll") \
        for (int j = 0; j < 12; j++) { \
            asm volatile("cp.async.cg.shared.global [%0], [%1], 16;" \
                :: "r"(dsto[j] + stoff), "l"(srcp[j] + koff)); \
        } \
        asm volatile("cp.async.commit_group;" ::: "memory"); \
    } while (0)

    ISSUE(0, 0);
    ISSUE(1, 1);

    float acc[4][8][4];
    #pragma unroll
    for (int mt = 0; mt < 4; mt++)
        #pragma unroll
        for (int nt = 0; nt < 8; nt++)
            #pragma unroll
            for (int j = 0; j < 4; j++) acc[mt][nt][j] = 0.0f;

    const int r4 = lane >> 2, c4 = lane & 3;

    for (int it = 0; it < KT; it++) {
        int sg = it % NSTG;
        asm volatile("cp.async.wait_group 1;" ::: "memory");
        __syncthreads();
        if (it + 2 < KT) { ISSUE(it + 2, (it + 2) % NSTG); }
        else { asm volatile("cp.async.commit_group;" ::: "memory"); }

        const __half* as_ = smh + sg * STGH;
        const __half* bs_ = as_ + AFLH;
        #pragma unroll
        for (int ks = 0; ks < 4; ks++) {
            int kbase = ks * 16 + 4 * c4;
            uint2 al[4], ah[4], bb[8];
            #pragma unroll
            for (int mt = 0; mt < 4; mt++) {
                int rr = wm + mt * 16 + r4;
                al[mt] = *(const uint2*)&as_[rr * LDSWH + kbase];
                ah[mt] = *(const uint2*)&as_[(rr + 8) * LDSWH + kbase];
            }
            #pragma unroll
            for (int nt = 0; nt < 8; nt++) {
                int rn = wn + nt * 8 + r4;
                bb[nt] = *(const uint2*)&bs_[rn * LDSWH + kbase];
            }
            #pragma unroll
            for (int mt = 0; mt < 4; mt++)
                #pragma unroll
                for (int nt = 0; nt < 8; nt++) {
                    asm volatile(
                        "mma.sync.aligned.m16n8k16.row.col.f32.f16.f16.f32 "
                        "{%0,%1,%2,%3}, {%4,%5,%6,%7}, {%8,%9}, {%0,%1,%2,%3};"
                        : "+f"(acc[mt][nt][0]), "+f"(acc[mt][nt][1]),
                          "+f"(acc[mt][nt][2]), "+f"(acc[mt][nt][3])
                        : "r"(al[mt].x), "r"(ah[mt].x), "r"(al[mt].y), "r"(ah[mt].y),
                          "r"(bb[nt].x), "r"(bb[nt].y));
                }
        }
    }

    // ---- epilogue ----
    #pragma unroll
    for (int mt = 0; mt < 4; mt++) {
        #pragma unroll
        for (int h = 0; h < 2; h++) {
            int rr = m0 + wm + mt * 16 + h * 8 + r4;
            long long rbase = (long long)rr * ldc;
            long long robase = resid ? ((long long)rr * ldr) : 0;
            #pragma unroll
            for (int nt = 0; nt < 8; nt++) {
                int col = n0 + wn + nt * 8 + c4 * 2;
                float v0 = acc[mt][nt][h * 2 + 0] * alpha;
                float v1 = acc[mt][nt][h * 2 + 1] * alpha;
                if (bias) { v0 += bias[col]; v1 += bias[col + 1]; }
                if (GELU) { v0 = gelu_f(v0); v1 = gelu_f(v1); }
                if (resid) { v0 += resid[robase + col]; v1 += resid[robase + col + 1]; }
                if (OUTH) {
                    __half2* C = (__half2*)((__half*)Cg + (long long)blockIdx.z * bsC + rbase + col);
                    *C = __floats2half2_rn(v0, v1);
                } else {
                    float* C = (float*)Cg + (long long)blockIdx.z * bsC + rbase + col;
                    *(float2*)C = make_float2(v0, v1);
                }
            }
        }
    }
    #undef ISSUE
}

// ---------------- transpose float -> half (R9-proven 32x32 version) ----------
__global__ void transpose_k(const float* __restrict__ in, __half* __restrict__ out,
                            int R, int Cc)
{
    __shared__ float t[32][33];
    int c0 = blockIdx.x * 32, r0 = blockIdx.y * 32;
    int x = threadIdx.x, y = threadIdx.y;
    #pragma unroll
    for (int dy = 0; dy < 32; dy += 8)
        t[y + dy][x] = in[(long long)(r0 + y + dy) * Cc + c0 + x];
    __syncthreads();
    #pragma unroll
    for (int dy = 0; dy < 32; dy += 8)
        out[(long long)(c0 + y + dy) * R + r0 + x] = __float2half(t[x][y + dy]);
}

// vT[z][d][m] = normalized v(m, z, d) from kvh layout (halves)
__global__ void vtrans_k(const __half* __restrict__ kvh, __half* __restrict__ vT)
{
    __shared__ __half t[32][40];
    int z = blockIdx.z; int b = z >> 4, h = z & 15;
    int m0 = blockIdx.y * 32, d0 = blockIdx.x * 32;
    int x = threadIdx.x, y = threadIdx.y;
    const __half* src = kvh + (long long)b * 4096 + h * 256 + 128 + d0 + x;
    #pragma unroll
    for (int dy = 0; dy < 32; dy += 8)
        t[y + dy][x] = src[(long long)(m0 + y + dy) * 8192];
    __syncthreads();
    __half* dst = vT + ((long long)z * 128 + d0) * 2048 + m0;
    #pragma unroll
    for (int dy = 0; dy < 32; dy += 8)
        dst[(long long)(y + dy) * 2048 + x] = t[x][y + dy];
}

// float -> half copy (mem_hidden)
__global__ void rcopy_k(const float* __restrict__ in, __half* __restrict__ out)
{
    long long i = (((long long)blockIdx.x * 256) + threadIdx.x) * 4;
    float4 v = *(const float4*)(in + i);
    __align__(8) __half2 o[2];
    o[0] = __floats2half2_rn(v.x, v.y);
    o[1] = __floats2half2_rn(v.z, v.w);
    *(uint2*)(out + i) = *(uint2*)o;
}

// ---------------- LayerNorm: float in, half out ----------------
__global__ void __launch_bounds__(256)
ln_k(const float* __restrict__ X, const float* __restrict__ gg,
     const float* __restrict__ bb, __half* __restrict__ Y)
{
    __shared__ float sh[8];
    long long base = (long long)blockIdx.x * CH;
    int c0 = threadIdx.x * 8;
    float v[8];
    *(float4*)(v)     = *(const float4*)(X + base + c0);
    *(float4*)(v + 4) = *(const float4*)(X + base + c0 + 4);
    float s = 0.f;
    #pragma unroll
    for (int i = 0; i < 8; i++) s += v[i];
    s = block_sum(s, sh);
    float mu = s * (1.0f / CH);
    float d[8], s2 = 0.f;
    #pragma unroll
    for (int i = 0; i < 8; i++) { d[i] = v[i] - mu; s2 += d[i] * d[i]; }
    s2 = block_sum(s2, sh);
    float rstd = rsqrtf(s2 * (1.0f / CH) + 1e-5f);
    __align__(16) __half2 o[4];
    #pragma unroll
    for (int i = 0; i < 4; i++) {
        float a = d[2*i]   * rstd * gg[c0 + 2*i]   + bb[c0 + 2*i];
        float b = d[2*i+1] * rstd * gg[c0 + 2*i+1] + bb[c0 + 2*i+1];
        o[i] = __floats2half2_rn(a, b);
    }
    *(uint4*)(Y + base + c0) = *(uint4*)o;
}

// ---------------- L2 normalize 128-chunks, half in-place ----------------
__global__ void __launch_bounds__(256)
l2h_k(__half* __restrict__ X)
{
    long long chunk = (long long)blockIdx.x * 8 + (threadIdx.x >> 5);
    int lane = threadIdx.x & 31;
    __half* p = X + chunk * 128 + lane * 4;
    __align__(8) __half2 h[2];
    *(uint2*)h = *(uint2*)p;
    float2 a = __half22float2(h[0]), b = __half22float2(h[1]);
    float s = a.x * a.x + a.y * a.y + b.x * b.x + b.y * b.y;
    #pragma unroll
    for (int o = 16; o > 0; o >>= 1) s += __shfl_xor_sync(0xffffffffu, s, o);
    float r = rsqrtf(s + 1e-12f);
    h[0] = __floats2half2_rn(a.x * r, a.y * r);
    h[1] = __floats2half2_rn(b.x * r, b.y * r);
    *(uint2*)p = *(uint2*)h;
}

// ---------------- masked softmax over M=2048, half in/out (in-place) --------
__global__ void __launch_bounds__(256)
softmax_k(__half* __restrict__ Sc, const void* __restrict__ maskp)
{
    __shared__ float sh[8];
    int r = blockIdx.x;
    int z = r >> 11, s = r & 2047;
    int b = z >> 4;
    __half* row = Sc + (long long)r * CMM;
    long long moff = ((long long)b * CS + s) * CMM;
    int mode = g_mask_mode;
    int c0 = threadIdx.x * 8;

    __align__(16) __half2 hv[4];
    *(uint4*)hv = *(uint4*)(row + c0);
    float v[8];
    #pragma unroll
    for (int i = 0; i < 4; i++) {
        float2 f = __half22float2(hv[i]);
        v[2*i] = f.x; v[2*i+1] = f.y;
    }

    if (mode == 0) {
        const unsigned char* mp = (const unsigned char*)maskp + moff + c0;
        #pragma unroll
        for (int i = 0; i < 8; i++) if (mp[i]) v[i] = -1e4f;
    } else if (mode == 1) {
        const int* mp = (const int*)maskp + moff + c0;
        #pragma unroll
        for (int i = 0; i < 8; i++) if (mp[i]) v[i] = -1e4f;
    } else {
        const float* mp = (const float*)maskp + moff + c0;
        #pragma unroll
        for (int i = 0; i < 8; i++) if (mp[i] != 0.0f) v[i] = -1e4f;
    }

    float mx = -3.4e38f;
    #pragma unroll
    for (int i = 0; i < 8; i++) mx = fmaxf(mx, v[i]);
    mx = block_max(mx, sh);
    float e[8], sum = 0.f;
    #pragma unroll
    for (int i = 0; i < 8; i++) { e[i] = __expf(v[i] - mx); sum += e[i]; }
    sum = block_sum(sum, sh);
    float inv = 1.0f / sum;
    __align__(16) __half2 o[4];
    #pragma unroll
    for (int i = 0; i < 4; i++)
        o[i] = __floats2half2_rn(e[2*i] * inv, e[2*i+1] * inv);
    *(uint4*)(row + c0) = *(uint4*)o;
}

// ---------------- launcher ----------------
extern "C" void kernel_launch(void* const* d_in, const int* in_sizes, int n_in,
                              void* d_out, int out_size)
{
    const float* x    = (const float*)d_in[0];
    const float* memh = (const float*)d_in[1];
    const void*  mask = d_in[2];
    const float* ln1g = (const float*)d_in[3];
    const float* ln1b = (const float*)d_in[4];
    const float* ln2g = (const float*)d_in[5];
    const float* ln2b = (const float*)d_in[6];
    const float* ln3g = (const float*)d_in[7];
    const float* ln3b = (const float*)d_in[8];
    const float* w1i  = (const float*)d_in[9];
    const float* b1i  = (const float*)d_in[10];
    const float* w1o  = (const float*)d_in[11];
    const float* b1o  = (const float*)d_in[12];
    const float* wq   = (const float*)d_in[13];
    const float* bq   = (const float*)d_in[14];
    const float* wkv  = (const float*)d_in[15];
    const float* bkv  = (const float*)d_in[16];
    const float* wd   = (const float*)d_in[17];
    const float* bd   = (const float*)d_in[18];
    const float* w2i  = (const float*)d_in[19];
    const float* b2i  = (const float*)d_in[20];
    const float* w2o  = (const float*)d_in[21];
    const float* b2o  = (const float*)d_in[22];
    float* out = (float*)d_out;

    __half *lnh, *hid, *qh, *kvh, *sch, *ctxh, *memhh, *vT;
    __half *w1iT, *w1oT, *wqT, *wkvT, *wdT, *w2iT, *w2oT;
    float *x1, *x2;
    cudaGetSymbolAddress((void**)&lnh,   g_lnh);
    cudaGetSymbolAddress((void**)&hid,   g_hid);
    cudaGetSymbolAddress((void**)&x1,    g_x1);
    cudaGetSymbolAddress((void**)&qh,    g_qh);
    cudaGetSymbolAddress((void**)&kvh,   g_kvh);
    cudaGetSymbolAddress((void**)&sch,   g_sch);
    cudaGetSymbolAddress((void**)&ctxh,  g_ctxh);
    cudaGetSymbolAddress((void**)&x2,    g_x2);
    cudaGetSymbolAddress((void**)&memhh, g_memh);
    cudaGetSymbolAddress((void**)&w1iT,  g_w1iT);
    cudaGetSymbolAddress((void**)&w1oT,  g_w1oT);
    cudaGetSymbolAddress((void**)&wqT,   g_wqT);
    cudaGetSymbolAddress((void**)&wkvT,  g_wkvT);
    cudaGetSymbolAddress((void**)&wdT,   g_wdT);
    cudaGetSymbolAddress((void**)&w2iT,  g_w2iT);
    cudaGetSymbolAddress((void**)&w2oT,  g_w2oT);
    cudaGetSymbolAddress((void**)&vT,    g_vT);

    cudaFuncSetAttribute(hgemm_k<true,  true >, cudaFuncAttributeMaxDynamicSharedMemorySize, SMEMB);
    cudaFuncSetAttribute(hgemm_k<false, false>, cudaFuncAttributeMaxDynamicSharedMemorySize, SMEMB);
    cudaFuncSetAttribute(hgemm_k<false, true >, cudaFuncAttributeMaxDynamicSharedMemorySize, SMEMB);

    dim3 tb(32, 8);

    // --- launch order arranged so ncu (-s 5 -c 1) profiles the MLP1-in GEMM ---
    detect_mask_k<<<1, 256>>>((const unsigned int*)mask);                 // 1
    ln_k<<<CR, 256>>>(x, ln1g, ln1b, lnh);                                // 2
    transpose_k<<<dim3(CFF/32, CH/32), tb>>>(w1i, w1iT, CH, CFF);         // 3
    rcopy_k<<<(CR * CH) / 1024, 256>>>(memh, memhh);                      // 4
    transpose_k<<<dim3(CH/32, CFF/32), tb>>>(w1o, w1oT, CFF, CH);         // 5
    hgemm_k<true, true><<<dim3(CFF/128, CR/256, 1), 256, SMEMB>>>(        // 6 (PROFILED)
        lnh, w1iT, hid, CH, CH, CH, CFF, 0, 0, 0, b1i, nullptr, 0, 1.0f);

    transpose_k<<<dim3(CH/32, CH/32),   tb>>>(wq,  wqT,  CH, CH);
    transpose_k<<<dim3(2*CH/32, CH/32), tb>>>(wkv, wkvT, CH, 2*CH);
    transpose_k<<<dim3(CH/32, CH/32),   tb>>>(wd,  wdT,  CH, CH);
    transpose_k<<<dim3(CFF/32, CH/32),  tb>>>(w2i, w2iT, CH, CFF);
    transpose_k<<<dim3(CH/32, CFF/32),  tb>>>(w2o, w2oT, CFF, CH);

    // x = mlp1(ln1(x)) (second half)
    hgemm_k<false, false><<<dim3(CH/128, CR/256, 1), 256, SMEMB>>>(
        hid, w1oT, x1, CFF, CFF, CFF, CH, 0, 0, 0, b1o, nullptr, 0, 1.0f);

    // memory attention
    ln_k<<<CR, 256>>>(x1, ln2g, ln2b, lnh);
    hgemm_k<false, true><<<dim3(CH/128, CR/256, 1), 256, SMEMB>>>(
        lnh, wqT, qh, CH, CH, CH, CH, 0, 0, 0, bq, nullptr, 0, 1.0f);
    l2h_k<<<CR * CH / 1024, 256>>>(qh);

    hgemm_k<false, true><<<dim3(2*CH/128, CR/256, 1), 256, SMEMB>>>(
        memhh, wkvT, kvh, CH, CH, CH, 2*CH, 0, 0, 0, bkv, nullptr, 0, 1.0f);
    l2h_k<<<CR * 2 * CH / 1024, 256>>>(kvh);
    vtrans_k<<<dim3(CD/32, CMM/32, NBATCH), tb>>>(kvh, vT);

    // scores = (q . k) / sqrt(D), half out, batched over z = b*16+h
    hgemm_k<false, true><<<dim3(CMM/128, CS/256, NBATCH), 256, SMEMB>>>(
        qh, kvh, sch, CD, 2*CH, 2*2*CH, CMM,
        128, 256, (long long)CS * CMM, nullptr, nullptr, 0, INV_NORM);

    softmax_k<<<NBATCH * CS, 256>>>(sch, mask);

    // ctx = probs @ v  via vT (NT form)
    hgemm_k<false, true><<<dim3(CD/128, CS/256, NBATCH), 256, SMEMB>>>(
        sch, vT, ctxh, CMM, CMM, CMM, 2*CH,
        (long long)CS * CMM, (long long)CD * CMM, 128, nullptr, nullptr, 0, 1.0f);

    // x2 = x1 + ctx @ w_dense + b_dense
    hgemm_k<false, false><<<dim3(CH/128, CR/256, 1), 256, SMEMB>>>(
        ctxh, wdT, x2, CH, CH, CH, CH, 0, 0, 0, bd, x1, CH, 1.0f);

    // out = x2 + mlp2(ln3(x2))
    ln_k<<<CR, 256>>>(x2, ln3g, ln3b, lnh);
    hgemm_k<true, true><<<dim3(CFF/128, CR/256, 1), 256, SMEMB>>>(
        lnh, w2iT, hid, CH, CH, CH, CFF, 0, 0, 0, b2i, nullptr, 0, 1.0f);
    hgemm_k<false, false><<<dim3(CH/128, CR/256, 1), 256, SMEMB>>>(
        hid, w2oT, out, CFF, CFF, CFF, CH, 0, 0, 0, b2o, x2, CH, 1.0f);
}